// round 1
// baseline (speedup 1.0000x reference)
#include <cuda_runtime.h>

// Problem constants (fixed by the dataset)
#define BB 4
#define SS 1024
#define DD 1024
#define HH 16
#define HD 64

// Scratch: __device__ globals (allocation-free rule)
static __device__ float g_q[BB * HH * SS * HD];   // q, pre-scaled by 1/sqrt(hd)
static __device__ float g_k[BB * HH * SS * HD];
static __device__ float g_v[BB * HH * SS * HD];
static __device__ float g_ao[BB * SS * DD];       // attention output [B,S,D]

// ---------------------------------------------------------------------------
// SGEMM: C[M,N] = A[M,K] @ B[K,N] + bias
// MODE 0: A = x, scatter epilogue into g_q/g_k/g_v (q scaled by 0.125)
// MODE 1: A = g_ao, plain epilogue into C (d_out)
// Tiling: 128x128 block, BK=16, 256 threads, 8x8 per thread.
// ---------------------------------------------------------------------------
template <int MODE>
__global__ void __launch_bounds__(256) sgemm_k(
    const float* __restrict__ A, const float* __restrict__ Bm,
    const float* __restrict__ bias, float* __restrict__ C,
    int M, int N, int K)
{
    __shared__ float As[16][132];  // transposed A tile: As[k][m]
    __shared__ float Bs[16][132];  // Bs[k][n]

    const int tid = threadIdx.x;
    const int tx = tid & 15;
    const int ty = tid >> 4;
    const int m0 = blockIdx.y * 128;
    const int n0 = blockIdx.x * 128;

    const float* Ap = (MODE == 1) ? (const float*)g_ao : A;

    float acc[8][8];
#pragma unroll
    for (int i = 0; i < 8; i++)
#pragma unroll
        for (int j = 0; j < 8; j++) acc[i][j] = 0.0f;

    for (int k0 = 0; k0 < K; k0 += 16) {
        // Load A tile (128 rows x 16 cols), store transposed
#pragma unroll
        for (int v = 0; v < 2; v++) {
            int li = tid + v * 256;            // 0..511
            int row = li >> 2;                 // 0..127
            int cv = li & 3;                   // float4 within the 16-col row
            float4 a = *(const float4*)(Ap + (size_t)(m0 + row) * K + k0 + cv * 4);
            As[cv * 4 + 0][row] = a.x;
            As[cv * 4 + 1][row] = a.y;
            As[cv * 4 + 2][row] = a.z;
            As[cv * 4 + 3][row] = a.w;
        }
        // Load B tile (16 rows x 128 cols)
#pragma unroll
        for (int v = 0; v < 2; v++) {
            int li = tid + v * 256;            // 0..511
            int row = li >> 5;                 // 0..15
            int cv = li & 31;                  // 32 float4 per row
            *(float4*)&Bs[row][cv * 4] =
                *(const float4*)(Bm + (size_t)(k0 + row) * N + n0 + cv * 4);
        }
        __syncthreads();

#pragma unroll
        for (int k = 0; k < 16; k++) {
            float ar[8], br[8];
            *(float4*)&ar[0] = *(float4*)&As[k][ty * 8];
            *(float4*)&ar[4] = *(float4*)&As[k][ty * 8 + 4];
            *(float4*)&br[0] = *(float4*)&Bs[k][tx * 8];
            *(float4*)&br[4] = *(float4*)&Bs[k][tx * 8 + 4];
#pragma unroll
            for (int i = 0; i < 8; i++)
#pragma unroll
                for (int j = 0; j < 8; j++)
                    acc[i][j] += ar[i] * br[j];
        }
        __syncthreads();
    }

    float bj[8];
#pragma unroll
    for (int j = 0; j < 8; j++) bj[j] = bias[n0 + tx * 8 + j];

    if (MODE == 0) {
        // Scatter qkv: n -> head h = n/192, segment (q|k|v), dim d = (n%192)&63
#pragma unroll
        for (int i = 0; i < 8; i++) {
            int m = m0 + ty * 8 + i;
            int bb = m >> 10;       // batch
            int srow = m & 1023;    // seq pos
#pragma unroll
            for (int j = 0; j < 8; j++) {
                int n = n0 + tx * 8 + j;
                float val = acc[i][j] + bj[j];
                int h = n / 192;
                int r = n - h * 192;
                int seg = r >> 6;
                int dd2 = r & 63;
                size_t idx = (((size_t)(bb * HH + h)) * SS + srow) * HD + dd2;
                if (seg == 0)      g_q[idx] = val * 0.125f;  // 1/sqrt(64)
                else if (seg == 1) g_k[idx] = val;
                else               g_v[idx] = val;
            }
        }
    } else {
#pragma unroll
        for (int i = 0; i < 8; i++) {
            int m = m0 + ty * 8 + i;
            float4 o0, o1;
            o0.x = acc[i][0] + bj[0]; o0.y = acc[i][1] + bj[1];
            o0.z = acc[i][2] + bj[2]; o0.w = acc[i][3] + bj[3];
            o1.x = acc[i][4] + bj[4]; o1.y = acc[i][5] + bj[5];
            o1.z = acc[i][6] + bj[6]; o1.w = acc[i][7] + bj[7];
            *(float4*)(C + (size_t)m * N + n0 + tx * 8)     = o0;
            *(float4*)(C + (size_t)m * N + n0 + tx * 8 + 4) = o1;
        }
    }
}

// ---------------------------------------------------------------------------
// Flash attention, fp32, 64-row Q tile per block, 64-row KV tiles, online
// softmax. Grid: (S/64, H, B). 256 threads = 16x16, each 4x4 micro-tile.
// Row statistics reduced across half-warp (16 threads with same ty).
// ---------------------------------------------------------------------------
#define PAD 68
#define ATTN_SMEM (4 * 64 * PAD * 4)

__global__ void __launch_bounds__(256) attn_k(const int* __restrict__ mask)
{
    extern __shared__ float sm[];
    float* Qs = sm;                 // [64 d][64 q] transposed, pad 68
    float* Ks = sm + 64 * PAD;      // [64 d][64 kv] transposed
    float* Vs = sm + 2 * 64 * PAD;  // [64 kv][64 d]
    float* Ps = sm + 3 * 64 * PAD;  // [64 q][64 kv]

    const int tid = threadIdx.x;
    const int tx = tid & 15;
    const int ty = tid >> 4;
    const int q0 = blockIdx.x * 64;
    const int h = blockIdx.y;
    const int b = blockIdx.z;
    const size_t bh = (size_t)(b * HH + h);
    const float* qb = g_q + bh * SS * HD;
    const float* kb = g_k + bh * SS * HD;
    const float* vb = g_v + bh * SS * HD;

    // Load Q tile transposed: Qs[d][q]
#pragma unroll
    for (int v = 0; v < 4; v++) {
        int idx = tid + v * 256;   // 0..1023
        int r = idx >> 4;          // q row 0..63
        int c4 = idx & 15;         // float4 index along d
        float4 qv = *(const float4*)(qb + (size_t)(q0 + r) * HD + c4 * 4);
        Qs[(c4 * 4 + 0) * PAD + r] = qv.x;
        Qs[(c4 * 4 + 1) * PAD + r] = qv.y;
        Qs[(c4 * 4 + 2) * PAD + r] = qv.z;
        Qs[(c4 * 4 + 3) * PAD + r] = qv.w;
    }

    float o[4][4];
    float mi[4], li[4];
#pragma unroll
    for (int i = 0; i < 4; i++) {
        mi[i] = -1e30f;
        li[i] = 0.0f;
#pragma unroll
        for (int j = 0; j < 4; j++) o[i][j] = 0.0f;
    }

    for (int t = 0; t < SS / 64; t++) {
        const int kv0 = t * 64;
        __syncthreads();  // prev PV done (and Q load visible on t=0)

        // Load K (transposed) and V tiles
#pragma unroll
        for (int v = 0; v < 4; v++) {
            int idx = tid + v * 256;
            int r = idx >> 4;
            int c4 = idx & 15;
            float4 kvv = *(const float4*)(kb + (size_t)(kv0 + r) * HD + c4 * 4);
            Ks[(c4 * 4 + 0) * PAD + r] = kvv.x;
            Ks[(c4 * 4 + 1) * PAD + r] = kvv.y;
            Ks[(c4 * 4 + 2) * PAD + r] = kvv.z;
            Ks[(c4 * 4 + 3) * PAD + r] = kvv.w;
            float4 vvv = *(const float4*)(vb + (size_t)(kv0 + r) * HD + c4 * 4);
            *(float4*)&Vs[r * PAD + c4 * 4] = vvv;
        }
        __syncthreads();

        // S = Q @ K^T (q already pre-scaled)
        float s[4][4];
#pragma unroll
        for (int i = 0; i < 4; i++)
#pragma unroll
            for (int j = 0; j < 4; j++) s[i][j] = 0.0f;

#pragma unroll 16
        for (int d = 0; d < 64; d++) {
            float4 qa = *(float4*)&Qs[d * PAD + ty * 4];
            float4 ka = *(float4*)&Ks[d * PAD + tx * 4];
            float qr[4] = {qa.x, qa.y, qa.z, qa.w};
            float kr[4] = {ka.x, ka.y, ka.z, ka.w};
#pragma unroll
            for (int i = 0; i < 4; i++)
#pragma unroll
                for (int j = 0; j < 4; j++)
                    s[i][j] += qr[i] * kr[j];
        }

        // Mask (int4-aligned direct gmem read)
#pragma unroll
        for (int i = 0; i < 4; i++) {
            const int4 mv = *(const int4*)(mask +
                ((size_t)b * SS + (q0 + ty * 4 + i)) * SS + kv0 + tx * 4);
            if (mv.x == 0) s[i][0] = -1e20f;
            if (mv.y == 0) s[i][1] = -1e20f;
            if (mv.z == 0) s[i][2] = -1e20f;
            if (mv.w == 0) s[i][3] = -1e20f;
        }

        // Online softmax
#pragma unroll
        for (int i = 0; i < 4; i++) {
            float mx = fmaxf(fmaxf(s[i][0], s[i][1]), fmaxf(s[i][2], s[i][3]));
#pragma unroll
            for (int off = 8; off > 0; off >>= 1)
                mx = fmaxf(mx, __shfl_xor_sync(0xffffffffu, mx, off, 16));
            float mnew = fmaxf(mi[i], mx);
            float alpha = __expf(mi[i] - mnew);
            float p0 = __expf(s[i][0] - mnew);
            float p1 = __expf(s[i][1] - mnew);
            float p2 = __expf(s[i][2] - mnew);
            float p3 = __expf(s[i][3] - mnew);
            float rs = p0 + p1 + p2 + p3;
#pragma unroll
            for (int off = 8; off > 0; off >>= 1)
                rs += __shfl_xor_sync(0xffffffffu, rs, off, 16);
            li[i] = li[i] * alpha + rs;
            mi[i] = mnew;
            o[i][0] *= alpha; o[i][1] *= alpha;
            o[i][2] *= alpha; o[i][3] *= alpha;
            float4 pv = make_float4(p0, p1, p2, p3);
            *(float4*)&Ps[(ty * 4 + i) * PAD + tx * 4] = pv;
        }
        __syncthreads();

        // O += P @ V
#pragma unroll 8
        for (int kk = 0; kk < 64; kk++) {
            float4 vv = *(float4*)&Vs[kk * PAD + tx * 4];
#pragma unroll
            for (int i = 0; i < 4; i++) {
                float p = Ps[(ty * 4 + i) * PAD + kk];
                o[i][0] += p * vv.x;
                o[i][1] += p * vv.y;
                o[i][2] += p * vv.z;
                o[i][3] += p * vv.w;
            }
        }
    }

    // Normalize and write [B,S,H,hd] = [B,S,D]
#pragma unroll
    for (int i = 0; i < 4; i++) {
        float inv = 1.0f / li[i];
        float4 ov = make_float4(o[i][0] * inv, o[i][1] * inv,
                                o[i][2] * inv, o[i][3] * inv);
        *(float4*)(g_ao + ((size_t)b * SS + (q0 + ty * 4 + i)) * DD + h * HD + tx * 4) = ov;
    }
}

// ---------------------------------------------------------------------------
extern "C" void kernel_launch(void* const* d_in, const int* in_sizes, int n_in,
                              void* d_out, int out_size)
{
    const float* x    = (const float*)d_in[0];
    const int*   mask = (const int*)  d_in[1];
    const float* Wqkv = (const float*)d_in[2];
    const float* bqkv = (const float*)d_in[3];
    const float* Wo   = (const float*)d_in[4];
    const float* bo   = (const float*)d_in[5];
    float* out = (float*)d_out;

    (void)in_sizes; (void)n_in; (void)out_size;

    // opt-in to >48KB dynamic smem for the attention kernel (idempotent)
    cudaFuncSetAttribute(attn_k, cudaFuncAttributeMaxDynamicSharedMemorySize, ATTN_SMEM);

    // 1) QKV projection: [4096,1024] @ [1024,3072] -> scatter to g_q/g_k/g_v
    {
        dim3 grid(3 * DD / 128, (BB * SS) / 128);
        sgemm_k<0><<<grid, 256>>>(x, Wqkv, bqkv, nullptr, BB * SS, 3 * DD, DD);
    }

    // 2) Flash attention -> g_ao [B,S,D]
    attn_k<<<dim3(SS / 64, HH, BB), 256, ATTN_SMEM>>>(mask);

    // 3) Output projection: [4096,1024] @ [1024,1024] + bo -> d_out
    {
        dim3 grid(DD / 128, (BB * SS) / 128);
        sgemm_k<1><<<grid, 256>>>(nullptr, Wo, bo, out, BB * SS, DD, DD);
    }
}

// round 2
// speedup vs baseline: 1.2636x; 1.2636x over previous
#include <cuda_runtime.h>
#include <mma.h>

using namespace nvcuda;

// Problem constants (fixed by the dataset)
#define BB 4
#define SS 1024
#define DD 1024
#define HH 16
#define HD 64

// Scratch: __device__ globals (allocation-free rule)
static __device__ float g_q[BB * HH * SS * HD];   // q, pre-scaled by 1/sqrt(hd)
static __device__ float g_k[BB * HH * SS * HD];
static __device__ float g_v[BB * HH * SS * HD];
static __device__ float g_ao[BB * SS * DD];       // attention output [B,S,D]

// ---------------------------------------------------------------------------
// tf32 WMMA GEMM: C[M,N] = A[M,K] @ B[K,N] + bias
// MODE 0: A = x, scatter epilogue into g_q/g_k/g_v (q scaled by 0.125)
// MODE 1: A = g_ao, plain epilogue into C (d_out)
// Block tile 128x128, BK=16, 256 threads (8 warps, 2x4), warp tile 64x32.
// Each warp: 4x2 wmma fragments of 16x16 (m16n16k8 tf32).
// ---------------------------------------------------------------------------
#define AS_LD 20
#define BS_LD 132

template <int MODE>
__global__ void __launch_bounds__(256) wgemm_k(
    const float* __restrict__ A, const float* __restrict__ Bm,
    const float* __restrict__ bias, float* __restrict__ C,
    int M, int N, int K)
{
    __shared__ float As[128][AS_LD];   // [m][k]
    __shared__ float Bs[16][BS_LD];    // [k][n]
    __shared__ float stage[8][16 * 16];

    const int tid  = threadIdx.x;
    const int lane = tid & 31;
    const int warp = tid >> 5;
    const int wm = (warp >> 2) * 64;   // warp row offset within block tile
    const int wn = (warp & 3) * 32;    // warp col offset
    const int m0 = blockIdx.y * 128;
    const int n0 = blockIdx.x * 128;

    const float* Ap = (MODE == 1) ? (const float*)g_ao : A;

    wmma::fragment<wmma::accumulator, 16, 16, 8, float> acc[4][2];
#pragma unroll
    for (int i = 0; i < 4; i++)
#pragma unroll
        for (int j = 0; j < 2; j++) wmma::fill_fragment(acc[i][j], 0.0f);

    // register staging for global loads (load-ahead)
    float4 rA[2], rB[2];

    // index precompute for loads
    const int arow = tid >> 2;          // 0..63 (x2 via +64)... see below
    const int acv  = tid & 3;
    const int brow = tid >> 5;          // 0..7 (x2 via +8)
    const int bcv  = tid & 31;

    // A tile: 128 rows x 16 cols = 512 float4; thread t handles li = t, t+256
    // li>>2 = row (0..127), li&3 = float4 column group
    // B tile: 16 rows x 128 cols = 512 float4; li>>5 = row, li&31 = col group
    auto loadG = [&](int k0) {
        rA[0] = *(const float4*)(Ap + (size_t)(m0 + arow) * K + k0 + acv * 4);
        rA[1] = *(const float4*)(Ap + (size_t)(m0 + arow + 64) * K + k0 + acv * 4);
        rB[0] = *(const float4*)(Bm + (size_t)(k0 + brow) * N + n0 + bcv * 4);
        rB[1] = *(const float4*)(Bm + (size_t)(k0 + brow + 8) * N + n0 + bcv * 4);
    };

    auto storeS = [&]() {
#pragma unroll
        for (int v = 0; v < 2; v++) {
            float* dst = &As[arow + v * 64][acv * 4];
            dst[0] = wmma::__float_to_tf32(rA[v].x);
            dst[1] = wmma::__float_to_tf32(rA[v].y);
            dst[2] = wmma::__float_to_tf32(rA[v].z);
            dst[3] = wmma::__float_to_tf32(rA[v].w);
            float* db = &Bs[brow + v * 8][bcv * 4];
            db[0] = wmma::__float_to_tf32(rB[v].x);
            db[1] = wmma::__float_to_tf32(rB[v].y);
            db[2] = wmma::__float_to_tf32(rB[v].z);
            db[3] = wmma::__float_to_tf32(rB[v].w);
        }
    };

    loadG(0);
    for (int k0 = 0; k0 < K; k0 += 16) {
        __syncthreads();
        storeS();
        __syncthreads();
        if (k0 + 16 < K) loadG(k0 + 16);

#pragma unroll
        for (int kk = 0; kk < 16; kk += 8) {
            wmma::fragment<wmma::matrix_a, 16, 16, 8, wmma::precision::tf32,
                           wmma::row_major> af[4];
            wmma::fragment<wmma::matrix_b, 16, 16, 8, wmma::precision::tf32,
                           wmma::row_major> bf[2];
#pragma unroll
            for (int mi = 0; mi < 4; mi++)
                wmma::load_matrix_sync(af[mi], &As[wm + mi * 16][kk], AS_LD);
#pragma unroll
            for (int ni = 0; ni < 2; ni++)
                wmma::load_matrix_sync(bf[ni], &Bs[kk][wn + ni * 16], BS_LD);
#pragma unroll
            for (int mi = 0; mi < 4; mi++)
#pragma unroll
                for (int ni = 0; ni < 2; ni++)
                    wmma::mma_sync(acc[mi][ni], af[mi], bf[ni], acc[mi][ni]);
        }
    }

    // -------------------- epilogue --------------------
    float* st = stage[warp];
    const int er = lane >> 1;          // staging row this lane handles
    const int ec = (lane & 1) * 8;     // staging col base (8 elems)

#pragma unroll
    for (int mi = 0; mi < 4; mi++) {
#pragma unroll
        for (int ni = 0; ni < 2; ni++) {
            __syncwarp();
            wmma::store_matrix_sync(st, acc[mi][ni], 16, wmma::mem_row_major);
            __syncwarp();

            const int row0 = m0 + wm + mi * 16;
            const int col0 = n0 + wn + ni * 16;
            const int m = row0 + er;
            float v[8];
#pragma unroll
            for (int j = 0; j < 8; j++)
                v[j] = st[er * 16 + ec + j] + bias[col0 + ec + j];

            if (MODE == 0) {
                // frag lies entirely within one (head, q|k|v) 64-wide segment
                const int h   = col0 / 192;
                const int r   = col0 - h * 192;
                const int seg = r >> 6;
                const int db  = (r & 63) + ec;
                const int bb  = m >> 10;
                const int srow = m & 1023;
                const size_t idx =
                    (((size_t)(bb * HH + h)) * SS + srow) * HD + db;
                if (seg == 0) {
#pragma unroll
                    for (int j = 0; j < 8; j++) v[j] *= 0.125f;
                    *(float4*)&g_q[idx]     = *(float4*)&v[0];
                    *(float4*)&g_q[idx + 4] = *(float4*)&v[4];
                } else if (seg == 1) {
                    *(float4*)&g_k[idx]     = *(float4*)&v[0];
                    *(float4*)&g_k[idx + 4] = *(float4*)&v[4];
                } else {
                    *(float4*)&g_v[idx]     = *(float4*)&v[0];
                    *(float4*)&g_v[idx + 4] = *(float4*)&v[4];
                }
            } else {
                float* dst = C + (size_t)m * N + col0 + ec;
                *(float4*)dst       = *(float4*)&v[0];
                *(float4*)(dst + 4) = *(float4*)&v[4];
            }
        }
    }
}

// ---------------------------------------------------------------------------
// Flash attention, fp32, 64-row Q tile per block, 64-row KV tiles, online
// softmax. Grid: (S/64, H, B). 256 threads = 16x16, each 4x4 micro-tile.
// ---------------------------------------------------------------------------
#define PAD 68
#define ATTN_SMEM (4 * 64 * PAD * 4)

__global__ void __launch_bounds__(256) attn_k(const int* __restrict__ mask)
{
    extern __shared__ float sm[];
    float* Qs = sm;                 // [64 d][64 q] transposed, pad 68
    float* Ks = sm + 64 * PAD;      // [64 d][64 kv] transposed
    float* Vs = sm + 2 * 64 * PAD;  // [64 kv][64 d]
    float* Ps = sm + 3 * 64 * PAD;  // [64 q][64 kv]

    const int tid = threadIdx.x;
    const int tx = tid & 15;
    const int ty = tid >> 4;
    const int q0 = blockIdx.x * 64;
    const int h = blockIdx.y;
    const int b = blockIdx.z;
    const size_t bh = (size_t)(b * HH + h);
    const float* qb = g_q + bh * SS * HD;
    const float* kb = g_k + bh * SS * HD;
    const float* vb = g_v + bh * SS * HD;

#pragma unroll
    for (int v = 0; v < 4; v++) {
        int idx = tid + v * 256;
        int r = idx >> 4;
        int c4 = idx & 15;
        float4 qv = *(const float4*)(qb + (size_t)(q0 + r) * HD + c4 * 4);
        Qs[(c4 * 4 + 0) * PAD + r] = qv.x;
        Qs[(c4 * 4 + 1) * PAD + r] = qv.y;
        Qs[(c4 * 4 + 2) * PAD + r] = qv.z;
        Qs[(c4 * 4 + 3) * PAD + r] = qv.w;
    }

    float o[4][4];
    float mi[4], li[4];
#pragma unroll
    for (int i = 0; i < 4; i++) {
        mi[i] = -1e30f;
        li[i] = 0.0f;
#pragma unroll
        for (int j = 0; j < 4; j++) o[i][j] = 0.0f;
    }

    for (int t = 0; t < SS / 64; t++) {
        const int kv0 = t * 64;
        __syncthreads();

#pragma unroll
        for (int v = 0; v < 4; v++) {
            int idx = tid + v * 256;
            int r = idx >> 4;
            int c4 = idx & 15;
            float4 kvv = *(const float4*)(kb + (size_t)(kv0 + r) * HD + c4 * 4);
            Ks[(c4 * 4 + 0) * PAD + r] = kvv.x;
            Ks[(c4 * 4 + 1) * PAD + r] = kvv.y;
            Ks[(c4 * 4 + 2) * PAD + r] = kvv.z;
            Ks[(c4 * 4 + 3) * PAD + r] = kvv.w;
            float4 vvv = *(const float4*)(vb + (size_t)(kv0 + r) * HD + c4 * 4);
            *(float4*)&Vs[r * PAD + c4 * 4] = vvv;
        }
        __syncthreads();

        float s[4][4];
#pragma unroll
        for (int i = 0; i < 4; i++)
#pragma unroll
            for (int j = 0; j < 4; j++) s[i][j] = 0.0f;

#pragma unroll 16
        for (int d = 0; d < 64; d++) {
            float4 qa = *(float4*)&Qs[d * PAD + ty * 4];
            float4 ka = *(float4*)&Ks[d * PAD + tx * 4];
            float qr[4] = {qa.x, qa.y, qa.z, qa.w};
            float kr[4] = {ka.x, ka.y, ka.z, ka.w};
#pragma unroll
            for (int i = 0; i < 4; i++)
#pragma unroll
                for (int j = 0; j < 4; j++)
                    s[i][j] += qr[i] * kr[j];
        }

#pragma unroll
        for (int i = 0; i < 4; i++) {
            const int4 mv = *(const int4*)(mask +
                ((size_t)b * SS + (q0 + ty * 4 + i)) * SS + kv0 + tx * 4);
            if (mv.x == 0) s[i][0] = -1e20f;
            if (mv.y == 0) s[i][1] = -1e20f;
            if (mv.z == 0) s[i][2] = -1e20f;
            if (mv.w == 0) s[i][3] = -1e20f;
        }

#pragma unroll
        for (int i = 0; i < 4; i++) {
            float mx = fmaxf(fmaxf(s[i][0], s[i][1]), fmaxf(s[i][2], s[i][3]));
#pragma unroll
            for (int off = 8; off > 0; off >>= 1)
                mx = fmaxf(mx, __shfl_xor_sync(0xffffffffu, mx, off, 16));
            float mnew = fmaxf(mi[i], mx);
            float alpha = __expf(mi[i] - mnew);
            float p0 = __expf(s[i][0] - mnew);
            float p1 = __expf(s[i][1] - mnew);
            float p2 = __expf(s[i][2] - mnew);
            float p3 = __expf(s[i][3] - mnew);
            float rs = p0 + p1 + p2 + p3;
#pragma unroll
            for (int off = 8; off > 0; off >>= 1)
                rs += __shfl_xor_sync(0xffffffffu, rs, off, 16);
            li[i] = li[i] * alpha + rs;
            mi[i] = mnew;
            o[i][0] *= alpha; o[i][1] *= alpha;
            o[i][2] *= alpha; o[i][3] *= alpha;
            float4 pv = make_float4(p0, p1, p2, p3);
            *(float4*)&Ps[(ty * 4 + i) * PAD + tx * 4] = pv;
        }
        __syncthreads();

#pragma unroll 8
        for (int kk = 0; kk < 64; kk++) {
            float4 vv = *(float4*)&Vs[kk * PAD + tx * 4];
#pragma unroll
            for (int i = 0; i < 4; i++) {
                float p = Ps[(ty * 4 + i) * PAD + kk];
                o[i][0] += p * vv.x;
                o[i][1] += p * vv.y;
                o[i][2] += p * vv.z;
                o[i][3] += p * vv.w;
            }
        }
    }

#pragma unroll
    for (int i = 0; i < 4; i++) {
        float inv = 1.0f / li[i];
        float4 ov = make_float4(o[i][0] * inv, o[i][1] * inv,
                                o[i][2] * inv, o[i][3] * inv);
        *(float4*)(g_ao + ((size_t)b * SS + (q0 + ty * 4 + i)) * DD + h * HD + tx * 4) = ov;
    }
}

// ---------------------------------------------------------------------------
extern "C" void kernel_launch(void* const* d_in, const int* in_sizes, int n_in,
                              void* d_out, int out_size)
{
    const float* x    = (const float*)d_in[0];
    const int*   mask = (const int*)  d_in[1];
    const float* Wqkv = (const float*)d_in[2];
    const float* bqkv = (const float*)d_in[3];
    const float* Wo   = (const float*)d_in[4];
    const float* bo   = (const float*)d_in[5];
    float* out = (float*)d_out;

    (void)in_sizes; (void)n_in; (void)out_size;

    cudaFuncSetAttribute(attn_k, cudaFuncAttributeMaxDynamicSharedMemorySize, ATTN_SMEM);

    // 1) QKV projection: [4096,1024] @ [1024,3072] -> scatter to g_q/g_k/g_v
    {
        dim3 grid(3 * DD / 128, (BB * SS) / 128);
        wgemm_k<0><<<grid, 256>>>(x, Wqkv, bqkv, nullptr, BB * SS, 3 * DD, DD);
    }

    // 2) Flash attention -> g_ao [B,S,D]
    attn_k<<<dim3(SS / 64, HH, BB), 256, ATTN_SMEM>>>(mask);

    // 3) Output projection: [4096,1024] @ [1024,1024] + bo -> d_out
    {
        dim3 grid(DD / 128, (BB * SS) / 128);
        wgemm_k<1><<<grid, 256>>>(nullptr, Wo, bo, out, BB * SS, DD, DD);
    }
}

// round 3
// speedup vs baseline: 1.4029x; 1.1102x over previous
#include <cuda_runtime.h>
#include <mma.h>

using namespace nvcuda;

#define BB 4
#define SS 1024
#define DD 1024
#define HH 16
#define HD 64

// Scratch (__device__ globals — allocation-free rule)
static __device__ float g_q[BB * HH * SS * HD];
static __device__ float g_k[BB * HH * SS * HD];
static __device__ float g_v[BB * HH * SS * HD];
static __device__ float g_ao[BB * SS * DD];
static __device__ float g_xr[BB * SS * DD];      // tf32-rounded x
static __device__ float g_wqkvr[DD * 3 * DD];    // tf32-rounded Wqkv
static __device__ float g_wor[DD * DD];          // tf32-rounded Wo

__device__ __forceinline__ void cpa16(void* dst, const void* src) {
    unsigned d = (unsigned)__cvta_generic_to_shared(dst);
    asm volatile("cp.async.cg.shared.global [%0], [%1], 16;\n" :: "r"(d), "l"(src));
}
#define CP_COMMIT() asm volatile("cp.async.commit_group;\n" ::)
#define CP_WAIT(N)  asm volatile("cp.async.wait_group %0;\n" :: "n"(N))

// ---------------------------------------------------------------------------
// tf32 RN pre-round pass: which 0->g_xr, 1->g_wqkvr, 2->g_wor
// ---------------------------------------------------------------------------
__global__ void round_k(const float4* __restrict__ src, int which, int n4) {
    float4* dst = which == 0 ? (float4*)g_xr
                : which == 1 ? (float4*)g_wqkvr : (float4*)g_wor;
    int i = blockIdx.x * blockDim.x + threadIdx.x;
    if (i < n4) {
        float4 v = src[i];
        v.x = wmma::__float_to_tf32(v.x);
        v.y = wmma::__float_to_tf32(v.y);
        v.z = wmma::__float_to_tf32(v.z);
        v.w = wmma::__float_to_tf32(v.w);
        dst[i] = v;
    }
}

// ---------------------------------------------------------------------------
// tf32 WMMA GEMM, 3-stage cp.async pipeline. 128x128 tile, BK=16, 256 thr.
// MODE 0: A=g_xr, B=g_wqkvr; epilogue scatters tf32-rounded q(*0.125)/k/v.
// MODE 1: A=g_ao, B=g_wor;   epilogue C = acc + bias (fp32, final out).
// Dynamic smem: As[3][128][20] (7680 f) + Bs[3][16][132] (6336 f) = 56064 B.
// ---------------------------------------------------------------------------
template <int MODE>
__global__ void __launch_bounds__(256, 2) wgemm_k(
    const float* __restrict__ bias, float* __restrict__ C, int N, int K)
{
    extern __shared__ float sm[];
    float* As = sm;            // stage stride 2560
    float* Bs = sm + 7680;     // stage stride 2112

    const int tid = threadIdx.x, lane = tid & 31, warp = tid >> 5;
    const int wm = (warp >> 2) * 64, wn = (warp & 3) * 32;
    const int m0 = blockIdx.y * 128, n0 = blockIdx.x * 128;

    const float* Ap = (MODE == 0) ? (const float*)g_xr    : (const float*)g_ao;
    const float* Bp = (MODE == 0) ? (const float*)g_wqkvr : (const float*)g_wor;

    const int ar0 = tid >> 2, ac = (tid & 3) * 4;
    const int br0 = tid >> 5, bc = (tid & 31) * 4;

    auto issue = [&](int st, int k0) {
        float* Ad = As + st * 2560;
        float* Bd = Bs + st * 2112;
        cpa16(&Ad[ar0 * 20 + ac],        Ap + (size_t)(m0 + ar0) * K + k0 + ac);
        cpa16(&Ad[(ar0 + 64) * 20 + ac], Ap + (size_t)(m0 + ar0 + 64) * K + k0 + ac);
        cpa16(&Bd[br0 * 132 + bc],       Bp + (size_t)(k0 + br0) * N + n0 + bc);
        cpa16(&Bd[(br0 + 8) * 132 + bc], Bp + (size_t)(k0 + br0 + 8) * N + n0 + bc);
    };

    wmma::fragment<wmma::accumulator, 16, 16, 8, float> acc[4][2];
#pragma unroll
    for (int i = 0; i < 4; i++)
#pragma unroll
        for (int j = 0; j < 2; j++) wmma::fill_fragment(acc[i][j], 0.0f);

    issue(0, 0);  CP_COMMIT();
    issue(1, 16); CP_COMMIT();
    issue(2, 32); CP_COMMIT();

    const int NI = K / 16;
    for (int i = 0; i < NI; i++) {
        const int st = i % 3;
        CP_WAIT(2);
        __syncthreads();
        const float* Ast = As + st * 2560;
        const float* Bst = Bs + st * 2112;
#pragma unroll
        for (int kk = 0; kk < 16; kk += 8) {
            wmma::fragment<wmma::matrix_a, 16, 16, 8, wmma::precision::tf32,
                           wmma::row_major> af[4];
            wmma::fragment<wmma::matrix_b, 16, 16, 8, wmma::precision::tf32,
                           wmma::row_major> bf[2];
#pragma unroll
            for (int mi = 0; mi < 4; mi++)
                wmma::load_matrix_sync(af[mi], &Ast[(wm + mi * 16) * 20 + kk], 20);
#pragma unroll
            for (int ni = 0; ni < 2; ni++)
                wmma::load_matrix_sync(bf[ni], &Bst[kk * 132 + wn + ni * 16], 132);
#pragma unroll
            for (int mi = 0; mi < 4; mi++)
#pragma unroll
                for (int ni = 0; ni < 2; ni++)
                    wmma::mma_sync(acc[mi][ni], af[mi], bf[ni], acc[mi][ni]);
        }
        __syncthreads();
        if (i + 3 < NI) issue(st, (i + 3) * 16);
        CP_COMMIT();
    }

    // epilogue — reuse As region as per-warp staging
    __syncthreads();
    float* stg = sm + warp * 256;
    const int er = lane >> 1;
    const int ec = (lane & 1) * 8;

#pragma unroll
    for (int mi = 0; mi < 4; mi++) {
#pragma unroll
        for (int ni = 0; ni < 2; ni++) {
            __syncwarp();
            wmma::store_matrix_sync(stg, acc[mi][ni], 16, wmma::mem_row_major);
            __syncwarp();

            const int row0 = m0 + wm + mi * 16;
            const int col0 = n0 + wn + ni * 16;
            const int m = row0 + er;
            float v[8];
#pragma unroll
            for (int j = 0; j < 8; j++)
                v[j] = stg[er * 16 + ec + j] + bias[col0 + ec + j];

            if (MODE == 0) {
                const int h   = col0 / 192;
                const int r   = col0 - h * 192;
                const int seg = r >> 6;
                const int db  = (r & 63) + ec;
                const int bb  = m >> 10;
                const int srow = m & 1023;
                const size_t idx =
                    (((size_t)(bb * HH + h)) * SS + srow) * HD + db;
                if (seg == 0) {
#pragma unroll
                    for (int j = 0; j < 8; j++)
                        v[j] = wmma::__float_to_tf32(v[j] * 0.125f);
                    *(float4*)&g_q[idx]     = *(float4*)&v[0];
                    *(float4*)&g_q[idx + 4] = *(float4*)&v[4];
                } else {
#pragma unroll
                    for (int j = 0; j < 8; j++)
                        v[j] = wmma::__float_to_tf32(v[j]);
                    float* dst = (seg == 1) ? g_k : g_v;
                    *(float4*)&dst[idx]     = *(float4*)&v[0];
                    *(float4*)&dst[idx + 4] = *(float4*)&v[4];
                }
            } else {
                float* dst = C + (size_t)m * N + col0 + ec;
                *(float4*)dst       = *(float4*)&v[0];
                *(float4*)(dst + 4) = *(float4*)&v[4];
            }
        }
    }
}

// ---------------------------------------------------------------------------
// Flash attention on wmma tf32. Block: 128 q rows of one (b,h). 8 warps.
// KV tile 64, double-buffered via cp.async. Per-warp 16-row strip.
// smem floats: Qs[128][72] | Ks[2][64][72] | Vs[2][64][72] | Ps[128][72] | Os[128][72]
// ---------------------------------------------------------------------------
#define QLD 72
#define NT (SS / 64)
#define ATTN_SMEM (46080 * 4)

__global__ void __launch_bounds__(256, 1) attn_k(const int* __restrict__ mask)
{
    extern __shared__ float sm[];
    float* Qs = sm;
    float* Ks = sm + 9216;
    float* Vs = sm + 18432;
    float* Ps = sm + 27648;
    float* Os = sm + 36864;

    const int tid = threadIdx.x, lane = tid & 31, warp = tid >> 5;
    const int q0 = blockIdx.x * 128;
    const int h = blockIdx.y, b = blockIdx.z;
    const size_t bh = (size_t)(b * HH + h);
    const float* qb = g_q + bh * SS * HD;
    const float* kb = g_k + bh * SS * HD;
    const float* vb = g_v + bh * SS * HD;

    // Q tile (already tf32-rounded in gmem)
#pragma unroll
    for (int j = 0; j < 8; j++) {
        int idx = tid + j * 256;
        int r = idx >> 4, c4 = idx & 15;
        *(float4*)&Qs[r * QLD + c4 * 4] =
            *(const float4*)(qb + (size_t)(q0 + r) * HD + c4 * 4);
    }

    // prefetch KV tile 0 into stage 0
#pragma unroll
    for (int j = 0; j < 4; j++) {
        int idx = tid + j * 256;
        int r = idx >> 4, c4 = idx & 15;
        cpa16(&Ks[r * QLD + c4 * 4], kb + (size_t)r * HD + c4 * 4);
        cpa16(&Vs[r * QLD + c4 * 4], vb + (size_t)r * HD + c4 * 4);
    }
    CP_COMMIT();

    const int r    = lane >> 1;
    const int cb   = (lane & 1) * 32;
    const int rowl = 16 * warp + r;           // local row owned for softmax/O
    float mi = -1e30f, li = 0.0f;

    for (int t = 0; t < NT; t++) {
        const int st = t & 1;
        if (t + 1 < NT) {
            const float* kb2 = kb + (size_t)(t + 1) * 64 * HD;
            const float* vb2 = vb + (size_t)(t + 1) * 64 * HD;
            float* Kd = Ks + (st ^ 1) * 4608;
            float* Vd = Vs + (st ^ 1) * 4608;
#pragma unroll
            for (int j = 0; j < 4; j++) {
                int idx = tid + j * 256;
                int rr = idx >> 4, c4 = idx & 15;
                cpa16(&Kd[rr * QLD + c4 * 4], kb2 + (size_t)rr * HD + c4 * 4);
                cpa16(&Vd[rr * QLD + c4 * 4], vb2 + (size_t)rr * HD + c4 * 4);
            }
        }
        CP_COMMIT();
        CP_WAIT(1);
        __syncthreads();

        const float* Kst = Ks + st * 4608;
        const float* Vst = Vs + st * 4608;
        float* Pw = &Ps[(16 * warp) * QLD];   // warp-private strip

        // ---- S = Q @ K^T (q pre-scaled) ----
        {
            wmma::fragment<wmma::accumulator, 16, 16, 8, float> sacc[4];
#pragma unroll
            for (int ni = 0; ni < 4; ni++) wmma::fill_fragment(sacc[ni], 0.0f);
#pragma unroll
            for (int kk = 0; kk < 8; kk++) {
                wmma::fragment<wmma::matrix_a, 16, 16, 8, wmma::precision::tf32,
                               wmma::row_major> aq;
                wmma::load_matrix_sync(aq, &Qs[(16 * warp) * QLD + kk * 8], QLD);
#pragma unroll
                for (int ni = 0; ni < 4; ni++) {
                    wmma::fragment<wmma::matrix_b, 16, 16, 8, wmma::precision::tf32,
                                   wmma::col_major> bk;
                    wmma::load_matrix_sync(bk, &Kst[(ni * 16) * QLD + kk * 8], QLD);
                    wmma::mma_sync(sacc[ni], aq, bk, sacc[ni]);
                }
            }
#pragma unroll
            for (int ni = 0; ni < 4; ni++)
                wmma::store_matrix_sync(&Pw[ni * 16], sacc[ni], QLD,
                                        wmma::mem_row_major);
        }
        __syncwarp();

        // ---- fused mask + online softmax (2 threads per row) ----
        float alphaR;
        {
            float* prow = &Ps[rowl * QLD + cb];
            const int* mrow =
                mask + ((size_t)b * SS + (q0 + rowl)) * SS + t * 64 + cb;
            float sv[32];
#pragma unroll
            for (int j = 0; j < 8; j++) {
                float4 s4 = *(float4*)&prow[j * 4];
                int4 m4 = *(const int4*)&mrow[j * 4];
                sv[j * 4 + 0] = m4.x != 0 ? s4.x : -1e20f;
                sv[j * 4 + 1] = m4.y != 0 ? s4.y : -1e20f;
                sv[j * 4 + 2] = m4.z != 0 ? s4.z : -1e20f;
                sv[j * 4 + 3] = m4.w != 0 ? s4.w : -1e20f;
            }
            float mx = sv[0];
#pragma unroll
            for (int j = 1; j < 32; j++) mx = fmaxf(mx, sv[j]);
            mx = fmaxf(mx, __shfl_xor_sync(0xffffffffu, mx, 1));
            float mnew = fmaxf(mi, mx);
            alphaR = __expf(mi - mnew);
            float rs = 0.0f;
#pragma unroll
            for (int j = 0; j < 32; j++) {
                sv[j] = __expf(sv[j] - mnew);
                rs += sv[j];
            }
            rs += __shfl_xor_sync(0xffffffffu, rs, 1);
            li = li * alphaR + rs;
            mi = mnew;
#pragma unroll
            for (int j = 0; j < 8; j++) {
                float4 p4 = make_float4(wmma::__float_to_tf32(sv[j * 4 + 0]),
                                        wmma::__float_to_tf32(sv[j * 4 + 1]),
                                        wmma::__float_to_tf32(sv[j * 4 + 2]),
                                        wmma::__float_to_tf32(sv[j * 4 + 3]));
                *(float4*)&prow[j * 4] = p4;
            }
        }
        __syncwarp();

        // ---- PV = P @ V into warp strip of Ps (staging) ----
        {
            wmma::fragment<wmma::accumulator, 16, 16, 8, float> oacc[4];
#pragma unroll
            for (int ni = 0; ni < 4; ni++) wmma::fill_fragment(oacc[ni], 0.0f);
#pragma unroll
            for (int kk = 0; kk < 8; kk++) {
                wmma::fragment<wmma::matrix_a, 16, 16, 8, wmma::precision::tf32,
                               wmma::row_major> ap;
                wmma::load_matrix_sync(ap, &Pw[kk * 8], QLD);
#pragma unroll
                for (int ni = 0; ni < 4; ni++) {
                    wmma::fragment<wmma::matrix_b, 16, 16, 8, wmma::precision::tf32,
                                   wmma::row_major> bv;
                    wmma::load_matrix_sync(bv, &Vst[(kk * 8) * QLD + ni * 16], QLD);
                    wmma::mma_sync(oacc[ni], ap, bv, oacc[ni]);
                }
            }
            __syncwarp();
#pragma unroll
            for (int ni = 0; ni < 4; ni++)
                wmma::store_matrix_sync(&Pw[ni * 16], oacc[ni], QLD,
                                        wmma::mem_row_major);
        }
        __syncwarp();

        // ---- O update: Os = alpha*Os + PV ----
        {
            float* psrc = &Ps[rowl * QLD + cb];
            float* odst = &Os[rowl * QLD + cb];
            if (t == 0) {
#pragma unroll
                for (int j = 0; j < 8; j++)
                    *(float4*)&odst[j * 4] = *(float4*)&psrc[j * 4];
            } else {
#pragma unroll
                for (int j = 0; j < 8; j++) {
                    float4 o4 = *(float4*)&odst[j * 4];
                    float4 p4 = *(float4*)&psrc[j * 4];
                    o4.x = o4.x * alphaR + p4.x;
                    o4.y = o4.y * alphaR + p4.y;
                    o4.z = o4.z * alphaR + p4.z;
                    o4.w = o4.w * alphaR + p4.w;
                    *(float4*)&odst[j * 4] = o4;
                }
            }
        }
        __syncthreads();   // stage (st^1) safe to refill next iter
    }

    // ---- normalize + write (tf32-rounded for next GEMM's cp.async) ----
    const float inv = 1.0f / li;
    float* osrc = &Os[rowl * QLD + cb];
    float* dst = g_ao + ((size_t)b * SS + (q0 + rowl)) * DD + h * HD + cb;
#pragma unroll
    for (int j = 0; j < 8; j++) {
        float4 o4 = *(float4*)&osrc[j * 4];
        o4.x = wmma::__float_to_tf32(o4.x * inv);
        o4.y = wmma::__float_to_tf32(o4.y * inv);
        o4.z = wmma::__float_to_tf32(o4.z * inv);
        o4.w = wmma::__float_to_tf32(o4.w * inv);
        *(float4*)&dst[j * 4] = o4;
    }
}

// ---------------------------------------------------------------------------
extern "C" void kernel_launch(void* const* d_in, const int* in_sizes, int n_in,
                              void* d_out, int out_size)
{
    const float* x    = (const float*)d_in[0];
    const int*   mask = (const int*)  d_in[1];
    const float* Wqkv = (const float*)d_in[2];
    const float* bqkv = (const float*)d_in[3];
    const float* Wo   = (const float*)d_in[4];
    const float* bo   = (const float*)d_in[5];
    float* out = (float*)d_out;
    (void)in_sizes; (void)n_in; (void)out_size;

    cudaFuncSetAttribute(attn_k, cudaFuncAttributeMaxDynamicSharedMemorySize,
                         ATTN_SMEM);
    cudaFuncSetAttribute(wgemm_k<0>, cudaFuncAttributeMaxDynamicSharedMemorySize,
                         56064);
    cudaFuncSetAttribute(wgemm_k<1>, cudaFuncAttributeMaxDynamicSharedMemorySize,
                         56064);

    // 0) tf32 RN pre-round of raw inputs
    round_k<<<(BB * SS * DD / 4 + 255) / 256, 256>>>((const float4*)x, 0,
                                                     BB * SS * DD / 4);
    round_k<<<(3 * DD * DD / 4 + 255) / 256, 256>>>((const float4*)Wqkv, 1,
                                                    3 * DD * DD / 4);
    round_k<<<(DD * DD / 4 + 255) / 256, 256>>>((const float4*)Wo, 2,
                                                DD * DD / 4);

    // 1) QKV projection -> q/k/v (tf32-rounded, q pre-scaled)
    {
        dim3 grid(3 * DD / 128, (BB * SS) / 128);
        wgemm_k<0><<<grid, 256, 56064>>>(bqkv, nullptr, 3 * DD, DD);
    }

    // 2) Flash attention (wmma tf32) -> g_ao
    attn_k<<<dim3(SS / 128, HH, BB), 256, ATTN_SMEM>>>(mask);

    // 3) Output projection -> d_out (fp32)
    {
        dim3 grid(DD / 128, (BB * SS) / 128);
        wgemm_k<1><<<grid, 256, 56064>>>(bo, out, DD, DD);
    }
}

// round 5
// speedup vs baseline: 1.7233x; 1.2284x over previous
#include <cuda_runtime.h>
#include <mma.h>
#include <cstdint>

using namespace nvcuda;

#define BB 4
#define SS 1024
#define DD 1024
#define HH 16
#define HD 64

// Scratch (__device__ globals — allocation-free rule)
static __device__ float g_q[BB * HH * SS * HD];
static __device__ float g_k[BB * HH * SS * HD];
static __device__ float g_v[BB * HH * SS * HD];
static __device__ float g_ao[BB * SS * DD];
static __device__ float g_xr[BB * SS * DD];      // tf32-rounded x
static __device__ float g_wqkvr[DD * 3 * DD];    // tf32-rounded Wqkv [K][N]
static __device__ float g_wor[DD * DD];          // tf32-rounded Wo   [K][N]

__device__ __forceinline__ void cpa16(void* dst, const void* src) {
    unsigned d = (unsigned)__cvta_generic_to_shared(dst);
    asm volatile("cp.async.cg.shared.global [%0], [%1], 16;\n" :: "r"(d), "l"(src));
}
#define CP_COMMIT() asm volatile("cp.async.commit_group;\n" ::)
#define CP_WAIT(N)  asm volatile("cp.async.wait_group %0;\n" :: "n"(N))

// m16n8k8 tf32 mma (A row-major, B col-major), D/C fp32, accumulate in place
__device__ __forceinline__ void mma8(float* d, const float* a,
                                     float b0, float b1) {
    asm volatile(
        "mma.sync.aligned.m16n8k8.row.col.f32.tf32.tf32.f32 "
        "{%0,%1,%2,%3}, {%4,%5,%6,%7}, {%8,%9}, {%0,%1,%2,%3};"
        : "+f"(d[0]), "+f"(d[1]), "+f"(d[2]), "+f"(d[3])
        : "r"(__float_as_uint(a[0])), "r"(__float_as_uint(a[1])),
          "r"(__float_as_uint(a[2])), "r"(__float_as_uint(a[3])),
          "r"(__float_as_uint(b0)), "r"(__float_as_uint(b1)));
}

// ---------------------------------------------------------------------------
// tf32 RN pre-round pass: which 0->g_xr, 1->g_wqkvr, 2->g_wor
// ---------------------------------------------------------------------------
__global__ void round_k(const float4* __restrict__ src, int which, int n4) {
    float4* dst = which == 0 ? (float4*)g_xr
                : which == 1 ? (float4*)g_wqkvr : (float4*)g_wor;
    int i = blockIdx.x * blockDim.x + threadIdx.x;
    if (i < n4) {
        float4 v = src[i];
        v.x = wmma::__float_to_tf32(v.x);
        v.y = wmma::__float_to_tf32(v.y);
        v.z = wmma::__float_to_tf32(v.z);
        v.w = wmma::__float_to_tf32(v.w);
        dst[i] = v;
    }
}

// ---------------------------------------------------------------------------
// tf32 WMMA GEMM, 3-stage cp.async pipeline (proven round-3 kernel).
// ---------------------------------------------------------------------------
template <int MODE>
__global__ void __launch_bounds__(256, 2) wgemm_k(
    const float* __restrict__ bias, float* __restrict__ C, int N, int K)
{
    extern __shared__ float sm[];
    float* As = sm;            // stage stride 2560
    float* Bs = sm + 7680;     // stage stride 2112

    const int tid = threadIdx.x, lane = tid & 31, warp = tid >> 5;
    const int wm = (warp >> 2) * 64, wn = (warp & 3) * 32;
    const int m0 = blockIdx.y * 128, n0 = blockIdx.x * 128;

    const float* Ap = (MODE == 0) ? (const float*)g_xr    : (const float*)g_ao;
    const float* Bp = (MODE == 0) ? (const float*)g_wqkvr : (const float*)g_wor;

    const int ar0 = tid >> 2, ac = (tid & 3) * 4;
    const int br0 = tid >> 5, bc = (tid & 31) * 4;

    auto issue = [&](int st, int k0) {
        float* Ad = As + st * 2560;
        float* Bd = Bs + st * 2112;
        cpa16(&Ad[ar0 * 20 + ac],        Ap + (size_t)(m0 + ar0) * K + k0 + ac);
        cpa16(&Ad[(ar0 + 64) * 20 + ac], Ap + (size_t)(m0 + ar0 + 64) * K + k0 + ac);
        cpa16(&Bd[br0 * 132 + bc],       Bp + (size_t)(k0 + br0) * N + n0 + bc);
        cpa16(&Bd[(br0 + 8) * 132 + bc], Bp + (size_t)(k0 + br0 + 8) * N + n0 + bc);
    };

    wmma::fragment<wmma::accumulator, 16, 16, 8, float> acc[4][2];
#pragma unroll
    for (int i = 0; i < 4; i++)
#pragma unroll
        for (int j = 0; j < 2; j++) wmma::fill_fragment(acc[i][j], 0.0f);

    issue(0, 0);  CP_COMMIT();
    issue(1, 16); CP_COMMIT();
    issue(2, 32); CP_COMMIT();

    const int NI = K / 16;
    for (int i = 0; i < NI; i++) {
        const int st = i % 3;
        CP_WAIT(2);
        __syncthreads();
        const float* Ast = As + st * 2560;
        const float* Bst = Bs + st * 2112;
#pragma unroll
        for (int kk = 0; kk < 16; kk += 8) {
            wmma::fragment<wmma::matrix_a, 16, 16, 8, wmma::precision::tf32,
                           wmma::row_major> af[4];
            wmma::fragment<wmma::matrix_b, 16, 16, 8, wmma::precision::tf32,
                           wmma::row_major> bf[2];
#pragma unroll
            for (int mi = 0; mi < 4; mi++)
                wmma::load_matrix_sync(af[mi], &Ast[(wm + mi * 16) * 20 + kk], 20);
#pragma unroll
            for (int ni = 0; ni < 2; ni++)
                wmma::load_matrix_sync(bf[ni], &Bst[kk * 132 + wn + ni * 16], 132);
#pragma unroll
            for (int mi = 0; mi < 4; mi++)
#pragma unroll
                for (int ni = 0; ni < 2; ni++)
                    wmma::mma_sync(acc[mi][ni], af[mi], bf[ni], acc[mi][ni]);
        }
        __syncthreads();
        if (i + 3 < NI) issue(st, (i + 3) * 16);
        CP_COMMIT();
    }

    __syncthreads();
    float* stg = sm + warp * 256;
    const int er = lane >> 1;
    const int ec = (lane & 1) * 8;

#pragma unroll
    for (int mi = 0; mi < 4; mi++) {
#pragma unroll
        for (int ni = 0; ni < 2; ni++) {
            __syncwarp();
            wmma::store_matrix_sync(stg, acc[mi][ni], 16, wmma::mem_row_major);
            __syncwarp();

            const int row0 = m0 + wm + mi * 16;
            const int col0 = n0 + wn + ni * 16;
            const int m = row0 + er;
            float v[8];
#pragma unroll
            for (int j = 0; j < 8; j++)
                v[j] = stg[er * 16 + ec + j] + bias[col0 + ec + j];

            if (MODE == 0) {
                const int h   = col0 / 192;
                const int r   = col0 - h * 192;
                const int seg = r >> 6;
                const int db  = (r & 63) + ec;
                const int bb  = m >> 10;
                const int srow = m & 1023;
                const size_t idx =
                    (((size_t)(bb * HH + h)) * SS + srow) * HD + db;
                if (seg == 0) {
#pragma unroll
                    for (int j = 0; j < 8; j++)
                        v[j] = wmma::__float_to_tf32(v[j] * 0.125f);
                    *(float4*)&g_q[idx]     = *(float4*)&v[0];
                    *(float4*)&g_q[idx + 4] = *(float4*)&v[4];
                } else {
#pragma unroll
                    for (int j = 0; j < 8; j++)
                        v[j] = wmma::__float_to_tf32(v[j]);
                    float* dst = (seg == 1) ? g_k : g_v;
                    *(float4*)&dst[idx]     = *(float4*)&v[0];
                    *(float4*)&dst[idx + 4] = *(float4*)&v[4];
                }
            } else {
                float* dst = C + (size_t)m * N + col0 + ec;
                *(float4*)dst       = *(float4*)&v[0];
                *(float4*)(dst + 4) = *(float4*)&v[4];
            }
        }
    }
}

// ---------------------------------------------------------------------------
// Flash attention v2: register-resident FA2 on mma.sync m16n8k8 tf32.
// Block: 128 q rows of one (b,h), 8 warps (16 q rows each). KV tile 64,
// double-buffered cp.async. S, softmax stats, O all in registers; P takes
// one warp-private smem round-trip to reshape D-frag -> A-frag.
//
// Fragment maps (PTX ISA, m16n8k8 tf32): g=lane>>2, tig=lane&3
//   A: a0(r=g,c=tig) a1(r=g+8,c=tig) a2(r=g,c=tig+4) a3(r=g+8,c=tig+4)
//   B: b0(k=tig,n=g) b1(k=tig+4,n=g)
//   D: d0(r=g,c=2tig) d1(r=g,c=2tig+1) d2(r=g+8,c=2tig) d3(r=g+8,c=2tig+1)
// smem floats: Qs[128][68] | Ks[2][64][68] | Vs[2][64][68] | Ps[128][68]
// ---------------------------------------------------------------------------
#define QLD 68
#define NT (SS / 64)
#define ATTN_SMEM (34816 * 4)

__global__ void __launch_bounds__(256, 1) attn_k(const int* __restrict__ mask)
{
    extern __shared__ float sm[];
    float* Qs = sm;                   // 128*68 = 8704
    float* Ks = sm + 8704;            // 2 stages of 64*68 = 4352
    float* Vs = sm + 17408;           // 2 stages
    float* Ps = sm + 26112;           // 128*68

    const int tid = threadIdx.x, lane = tid & 31, warp = tid >> 5;
    const int g = lane >> 2, tig = lane & 3;
    const int q0 = blockIdx.x * 128;
    const int h = blockIdx.y, b = blockIdx.z;
    const size_t bh = (size_t)(b * HH + h);
    const float* qb = g_q + bh * SS * HD;
    const float* kb = g_k + bh * SS * HD;
    const float* vb = g_v + bh * SS * HD;

    // Q tile -> smem (straight copy; already tf32-rounded)
#pragma unroll
    for (int j = 0; j < 8; j++) {
        int idx = tid + j * 256;
        int r = idx >> 4, c4 = idx & 15;
        *(float4*)&Qs[r * QLD + c4 * 4] =
            *(const float4*)(qb + (size_t)(q0 + r) * HD + c4 * 4);
    }
    // prefetch KV tile 0 -> stage 0
#pragma unroll
    for (int j = 0; j < 4; j++) {
        int idx = tid + j * 256;
        int r = idx >> 4, c4 = idx & 15;
        cpa16(&Ks[r * QLD + c4 * 4], kb + (size_t)r * HD + c4 * 4);
        cpa16(&Vs[r * QLD + c4 * 4], vb + (size_t)r * HD + c4 * 4);
    }
    CP_COMMIT();
    __syncthreads();

    const int r0 = 16 * warp + g;     // local q rows owned by this thread
    const int r1 = r0 + 8;

    // preload Q A-fragments for all 8 k-steps (resident whole kernel)
    float qf[8][4];
#pragma unroll
    for (int kk = 0; kk < 8; kk++) {
        qf[kk][0] = Qs[r0 * QLD + kk * 8 + tig];
        qf[kk][1] = Qs[r1 * QLD + kk * 8 + tig];
        qf[kk][2] = Qs[r0 * QLD + kk * 8 + tig + 4];
        qf[kk][3] = Qs[r1 * QLD + kk * 8 + tig + 4];
    }

    float o[8][4];
#pragma unroll
    for (int j = 0; j < 8; j++)
#pragma unroll
        for (int c = 0; c < 4; c++) o[j][c] = 0.0f;
    float mi0 = -1e30f, mi1 = -1e30f, li0 = 0.0f, li1 = 0.0f;

    const int* mrow0 = mask + ((size_t)b * SS + (q0 + r0)) * SS;
    const int* mrow1 = mask + ((size_t)b * SS + (q0 + r1)) * SS;

    for (int t = 0; t < NT; t++) {
        const int st = t & 1;
        if (t + 1 < NT) {
            const float* kb2 = kb + (size_t)(t + 1) * 64 * HD;
            const float* vb2 = vb + (size_t)(t + 1) * 64 * HD;
            float* Kd = Ks + (st ^ 1) * 4352;
            float* Vd = Vs + (st ^ 1) * 4352;
#pragma unroll
            for (int j = 0; j < 4; j++) {
                int idx = tid + j * 256;
                int rr = idx >> 4, c4 = idx & 15;
                cpa16(&Kd[rr * QLD + c4 * 4], kb2 + (size_t)rr * HD + c4 * 4);
                cpa16(&Vd[rr * QLD + c4 * 4], vb2 + (size_t)rr * HD + c4 * 4);
            }
        }
        CP_COMMIT();
        CP_WAIT(1);
        __syncthreads();

        const float* Kst = Ks + st * 4352;
        const float* Vst = Vs + st * 4352;
        const int kv0 = t * 64;

        // ---- S = Q @ K^T (registers) ----
        float s[8][4];
#pragma unroll
        for (int j = 0; j < 8; j++) {
            s[j][0] = s[j][1] = s[j][2] = s[j][3] = 0.0f;
            const float* krow = &Kst[(j * 8 + g) * QLD];
#pragma unroll
            for (int kk = 0; kk < 8; kk++)
                mma8(s[j], qf[kk], krow[kk * 8 + tig], krow[kk * 8 + tig + 4]);
        }

        // ---- mask ----
#pragma unroll
        for (int j = 0; j < 8; j++) {
            int2 m0v = *(const int2*)(mrow0 + kv0 + j * 8 + 2 * tig);
            int2 m1v = *(const int2*)(mrow1 + kv0 + j * 8 + 2 * tig);
            if (m0v.x == 0) s[j][0] = -1e20f;
            if (m0v.y == 0) s[j][1] = -1e20f;
            if (m1v.x == 0) s[j][2] = -1e20f;
            if (m1v.y == 0) s[j][3] = -1e20f;
        }

        // ---- online softmax (row stats across 4-lane group) ----
        float mx0 = s[0][0], mx1 = s[0][2];
#pragma unroll
        for (int j = 0; j < 8; j++) {
            mx0 = fmaxf(mx0, fmaxf(s[j][0], s[j][1]));
            mx1 = fmaxf(mx1, fmaxf(s[j][2], s[j][3]));
        }
        mx0 = fmaxf(mx0, __shfl_xor_sync(0xffffffffu, mx0, 1));
        mx0 = fmaxf(mx0, __shfl_xor_sync(0xffffffffu, mx0, 2));
        mx1 = fmaxf(mx1, __shfl_xor_sync(0xffffffffu, mx1, 1));
        mx1 = fmaxf(mx1, __shfl_xor_sync(0xffffffffu, mx1, 2));
        const float mn0 = fmaxf(mi0, mx0), mn1 = fmaxf(mi1, mx1);
        const float a0 = __expf(mi0 - mn0), a1 = __expf(mi1 - mn1);
        float rs0 = 0.0f, rs1 = 0.0f;
#pragma unroll
        for (int j = 0; j < 8; j++) {
            s[j][0] = __expf(s[j][0] - mn0);
            s[j][1] = __expf(s[j][1] - mn0);
            s[j][2] = __expf(s[j][2] - mn1);
            s[j][3] = __expf(s[j][3] - mn1);
            rs0 += s[j][0] + s[j][1];
            rs1 += s[j][2] + s[j][3];
        }
        rs0 += __shfl_xor_sync(0xffffffffu, rs0, 1);
        rs0 += __shfl_xor_sync(0xffffffffu, rs0, 2);
        rs1 += __shfl_xor_sync(0xffffffffu, rs1, 1);
        rs1 += __shfl_xor_sync(0xffffffffu, rs1, 2);
        li0 = li0 * a0 + rs0; li1 = li1 * a1 + rs1;
        mi0 = mn0; mi1 = mn1;
#pragma unroll
        for (int j = 0; j < 8; j++) {
            o[j][0] *= a0; o[j][1] *= a0;
            o[j][2] *= a1; o[j][3] *= a1;
        }

        // ---- P -> warp-private smem strip (tf32) ----
#pragma unroll
        for (int j = 0; j < 8; j++) {
            float2 p01 = make_float2(wmma::__float_to_tf32(s[j][0]),
                                     wmma::__float_to_tf32(s[j][1]));
            float2 p23 = make_float2(wmma::__float_to_tf32(s[j][2]),
                                     wmma::__float_to_tf32(s[j][3]));
            *(float2*)&Ps[r0 * QLD + j * 8 + 2 * tig] = p01;
            *(float2*)&Ps[r1 * QLD + j * 8 + 2 * tig] = p23;
        }
        __syncwarp();

        // ---- reload P as A-fragments ----
        float pa[8][4];
#pragma unroll
        for (int kk = 0; kk < 8; kk++) {
            pa[kk][0] = Ps[r0 * QLD + kk * 8 + tig];
            pa[kk][1] = Ps[r1 * QLD + kk * 8 + tig];
            pa[kk][2] = Ps[r0 * QLD + kk * 8 + tig + 4];
            pa[kk][3] = Ps[r1 * QLD + kk * 8 + tig + 4];
        }

        // ---- O += P @ V ----
#pragma unroll
        for (int kk = 0; kk < 8; kk++) {
            const float* v0 = &Vst[(kk * 8 + tig) * QLD];
            const float* v1 = &Vst[(kk * 8 + tig + 4) * QLD];
#pragma unroll
            for (int j = 0; j < 8; j++)
                mma8(o[j], pa[kk], v0[j * 8 + g], v1[j * 8 + g]);
        }
        __syncthreads();   // all warps done with stage st^1 reads
    }

    // ---- normalize + write g_ao (tf32-rounded for next GEMM) ----
    const float inv0 = 1.0f / li0, inv1 = 1.0f / li1;
    float* dst0 = g_ao + ((size_t)b * SS + (q0 + r0)) * DD + h * HD;
    float* dst1 = g_ao + ((size_t)b * SS + (q0 + r1)) * DD + h * HD;
#pragma unroll
    for (int j = 0; j < 8; j++) {
        float2 w0 = make_float2(wmma::__float_to_tf32(o[j][0] * inv0),
                                wmma::__float_to_tf32(o[j][1] * inv0));
        float2 w1 = make_float2(wmma::__float_to_tf32(o[j][2] * inv1),
                                wmma::__float_to_tf32(o[j][3] * inv1));
        *(float2*)&dst0[j * 8 + 2 * tig] = w0;
        *(float2*)&dst1[j * 8 + 2 * tig] = w1;
    }
}

// ---------------------------------------------------------------------------
extern "C" void kernel_launch(void* const* d_in, const int* in_sizes, int n_in,
                              void* d_out, int out_size)
{
    const float* x    = (const float*)d_in[0];
    const int*   mask = (const int*)  d_in[1];
    const float* Wqkv = (const float*)d_in[2];
    const float* bqkv = (const float*)d_in[3];
    const float* Wo   = (const float*)d_in[4];
    const float* bo   = (const float*)d_in[5];
    float* out = (float*)d_out;
    (void)in_sizes; (void)n_in; (void)out_size;

    cudaFuncSetAttribute(attn_k, cudaFuncAttributeMaxDynamicSharedMemorySize,
                         ATTN_SMEM);
    cudaFuncSetAttribute(wgemm_k<0>, cudaFuncAttributeMaxDynamicSharedMemorySize,
                         56064);
    cudaFuncSetAttribute(wgemm_k<1>, cudaFuncAttributeMaxDynamicSharedMemorySize,
                         56064);

    // 0) tf32 RN pre-round of raw inputs
    round_k<<<(BB * SS * DD / 4 + 255) / 256, 256>>>((const float4*)x, 0,
                                                     BB * SS * DD / 4);
    round_k<<<(3 * DD * DD / 4 + 255) / 256, 256>>>((const float4*)Wqkv, 1,
                                                    3 * DD * DD / 4);
    round_k<<<(DD * DD / 4 + 255) / 256, 256>>>((const float4*)Wo, 2,
                                                DD * DD / 4);

    // 1) QKV projection -> q/k/v (tf32-rounded, q pre-scaled)
    {
        dim3 grid(3 * DD / 128, (BB * SS) / 128);
        wgemm_k<0><<<grid, 256, 56064>>>(bqkv, nullptr, 3 * DD, DD);
    }

    // 2) Flash attention (mma.sync tf32, register-resident) -> g_ao
    attn_k<<<dim3(SS / 128, HH, BB), 256, ATTN_SMEM>>>(mask);

    // 3) Output projection -> d_out (fp32)
    {
        dim3 grid(DD / 128, (BB * SS) / 128);
        wgemm_k<1><<<grid, 256, 56064>>>(bo, out, DD, DD);
    }
}

// round 6
// speedup vs baseline: 2.8666x; 1.6634x over previous
#include <cuda_runtime.h>
#include <mma.h>
#include <cstdint>

using namespace nvcuda;

#define BB 4
#define SS 1024
#define DD 1024
#define HH 16
#define HD 64

// Scratch (__device__ globals — allocation-free rule)
static __device__ float g_q[BB * HH * SS * HD];
static __device__ float g_k[BB * HH * SS * HD];
static __device__ float g_v[BB * HH * SS * HD];
static __device__ float g_ao[BB * SS * DD];
static __device__ float g_xr[BB * SS * DD];      // tf32-rounded x
static __device__ float g_wqkvr[DD * 3 * DD];    // tf32-rounded Wqkv [K][N]
static __device__ float g_wor[DD * DD];          // tf32-rounded Wo   [K][N]

__device__ __forceinline__ void cpa16(void* dst, const void* src) {
    unsigned d = (unsigned)__cvta_generic_to_shared(dst);
    asm volatile("cp.async.cg.shared.global [%0], [%1], 16;\n" :: "r"(d), "l"(src));
}
#define CP_COMMIT() asm volatile("cp.async.commit_group;\n" ::)
#define CP_WAIT(N)  asm volatile("cp.async.wait_group %0;\n" :: "n"(N))

// m16n8k8 tf32 mma (A row-major, B col-major), D/C fp32, accumulate in place
__device__ __forceinline__ void mma8(float* d, const float* a,
                                     float b0, float b1) {
    asm volatile(
        "mma.sync.aligned.m16n8k8.row.col.f32.tf32.tf32.f32 "
        "{%0,%1,%2,%3}, {%4,%5,%6,%7}, {%8,%9}, {%0,%1,%2,%3};"
        : "+f"(d[0]), "+f"(d[1]), "+f"(d[2]), "+f"(d[3])
        : "r"(__float_as_uint(a[0])), "r"(__float_as_uint(a[1])),
          "r"(__float_as_uint(a[2])), "r"(__float_as_uint(a[3])),
          "r"(__float_as_uint(b0)), "r"(__float_as_uint(b1)));
}

// ---------------------------------------------------------------------------
// tf32 RN pre-round pass: which 0->g_xr, 1->g_wqkvr, 2->g_wor
// ---------------------------------------------------------------------------
__global__ void round_k(const float4* __restrict__ src, int which, int n4) {
    float4* dst = which == 0 ? (float4*)g_xr
                : which == 1 ? (float4*)g_wqkvr : (float4*)g_wor;
    int i = blockIdx.x * blockDim.x + threadIdx.x;
    if (i < n4) {
        float4 v = src[i];
        v.x = wmma::__float_to_tf32(v.x);
        v.y = wmma::__float_to_tf32(v.y);
        v.z = wmma::__float_to_tf32(v.z);
        v.w = wmma::__float_to_tf32(v.w);
        dst[i] = v;
    }
}

// ---------------------------------------------------------------------------
// Raw mma.sync tf32 GEMM. CTA tile 128x128, BK=16, 256 thr (8 warps 2x4,
// warp tile 64x32). 4-stage cp.async ring, 1 barrier/slab.
// smem per stage: A[128][20] (2560 f) + B[16][136] (2176 f) = stride 4736 f.
// MODE 0: A=g_xr, B=g_wqkvr -> scatter q(*0.125)/k/v (tf32-rounded)
// MODE 1: A=g_ao, B=g_wor -> C = acc + bias (fp32)
// ---------------------------------------------------------------------------
#define GSTG 4736
#define GSMEM (4 * GSTG * 4)

template <int MODE>
__global__ void __launch_bounds__(256, 2) mgemm_k(
    const float* __restrict__ bias, float* __restrict__ C, int N, int K)
{
    extern __shared__ float sm[];

    const int tid = threadIdx.x, lane = tid & 31, warp = tid >> 5;
    const int g = lane >> 2, tig = lane & 3;
    const int wm = (warp >> 2) * 64, wn = (warp & 3) * 32;
    const int m0 = blockIdx.y * 128, n0 = blockIdx.x * 128;

    const float* Ap = (MODE == 0) ? (const float*)g_xr    : (const float*)g_ao;
    const float* Bp = (MODE == 0) ? (const float*)g_wqkvr : (const float*)g_wor;

    // load indices: A 512 float4 (row=id>>2, c=id&3); B 512 float4 (row=id>>5, col=id&31)
    const int ar = tid >> 2, ac = (tid & 3) * 4;
    const int br = tid >> 5, bc = (tid & 31) * 4;

    auto issue = [&](int st, int k0) {
        float* As = sm + st * GSTG;
        float* Bs = As + 2560;
        cpa16(&As[ar * 20 + ac],         Ap + (size_t)(m0 + ar) * K + k0 + ac);
        cpa16(&As[(ar + 64) * 20 + ac],  Ap + (size_t)(m0 + ar + 64) * K + k0 + ac);
        cpa16(&Bs[br * 136 + bc],        Bp + (size_t)(k0 + br) * N + n0 + bc);
        cpa16(&Bs[(br + 8) * 136 + bc],  Bp + (size_t)(k0 + br + 8) * N + n0 + bc);
    };

    float d[4][4][4];
#pragma unroll
    for (int mf = 0; mf < 4; mf++)
#pragma unroll
        for (int nf = 0; nf < 4; nf++)
#pragma unroll
            for (int c = 0; c < 4; c++) d[mf][nf][c] = 0.0f;

    issue(0, 0);  CP_COMMIT();
    issue(1, 16); CP_COMMIT();
    issue(2, 32); CP_COMMIT();

    const int NI = K / 16;
    for (int i = 0; i < NI; i++) {
        const int st = i & 3;
        CP_WAIT(2);
        __syncthreads();
        if (i + 3 < NI) issue((i + 3) & 3, (i + 3) * 16);
        CP_COMMIT();

        const float* As = sm + st * GSTG;
        const float* Bs = As + 2560;

        // software-pipelined frag loads over the 2 k-steps
        float af[2][4][4], bf[2][4][2];
#pragma unroll
        for (int mf = 0; mf < 4; mf++) {
            const float* a0 = &As[(wm + mf * 16 + g) * 20 + tig];
            const float* a1 = &As[(wm + mf * 16 + g + 8) * 20 + tig];
            af[0][mf][0] = a0[0]; af[0][mf][1] = a1[0];
            af[0][mf][2] = a0[4]; af[0][mf][3] = a1[4];
        }
#pragma unroll
        for (int nf = 0; nf < 4; nf++) {
            bf[0][nf][0] = Bs[tig * 136 + wn + nf * 8 + g];
            bf[0][nf][1] = Bs[(tig + 4) * 136 + wn + nf * 8 + g];
        }
#pragma unroll
        for (int kk = 0; kk < 2; kk++) {
            if (kk == 0) {
#pragma unroll
                for (int mf = 0; mf < 4; mf++) {
                    const float* a0 = &As[(wm + mf * 16 + g) * 20 + 8 + tig];
                    const float* a1 = &As[(wm + mf * 16 + g + 8) * 20 + 8 + tig];
                    af[1][mf][0] = a0[0]; af[1][mf][1] = a1[0];
                    af[1][mf][2] = a0[4]; af[1][mf][3] = a1[4];
                }
#pragma unroll
                for (int nf = 0; nf < 4; nf++) {
                    bf[1][nf][0] = Bs[(8 + tig) * 136 + wn + nf * 8 + g];
                    bf[1][nf][1] = Bs[(12 + tig) * 136 + wn + nf * 8 + g];
                }
            }
#pragma unroll
            for (int mf = 0; mf < 4; mf++)
#pragma unroll
                for (int nf = 0; nf < 4; nf++)
                    mma8(d[mf][nf], af[kk][mf], bf[kk][nf][0], bf[kk][nf][1]);
        }
    }

    // ---- direct epilogue (D-frag: rows g,g+8; cols 2tig,2tig+1) ----
#pragma unroll
    for (int mf = 0; mf < 4; mf++) {
        const int m = m0 + wm + mf * 16 + g;
        const int bb = m >> 10, srow = m & 1023;
#pragma unroll
        for (int nf = 0; nf < 4; nf++) {
            const int col0 = n0 + wn + nf * 8 + 2 * tig;
            const float b0 = bias[col0], b1 = bias[col0 + 1];
            float v0 = d[mf][nf][0] + b0, v1 = d[mf][nf][1] + b1;
            float v2 = d[mf][nf][2] + b0, v3 = d[mf][nf][3] + b1;

            if (MODE == 0) {
                const int h = col0 / 192;
                const int rr = col0 - h * 192;
                const int seg = rr >> 6;
                const int db = rr & 63;
                const size_t idx =
                    (((size_t)(bb * HH + h)) * SS + srow) * HD + db;
                float* dst = (seg == 0) ? g_q : (seg == 1) ? g_k : g_v;
                const float sc = (seg == 0) ? 0.125f : 1.0f;
                float2 w0 = make_float2(wmma::__float_to_tf32(v0 * sc),
                                        wmma::__float_to_tf32(v1 * sc));
                float2 w1 = make_float2(wmma::__float_to_tf32(v2 * sc),
                                        wmma::__float_to_tf32(v3 * sc));
                *(float2*)&dst[idx]           = w0;
                *(float2*)&dst[idx + 8 * HD]  = w1;
            } else {
                float* dst = C + (size_t)m * N + col0;
                *(float2*)dst           = make_float2(v0, v1);
                *(float2*)(dst + 8 * N) = make_float2(v2, v3);
            }
        }
    }
}

// ---------------------------------------------------------------------------
// Flash attention FA2 on mma.sync tf32, register-resident. P transported
// D-frag -> A-frag via shfl (no smem P buffer) => 2 CTAs/SM.
// smem floats: Qs[128][68] | Ks[2][64][68] | Vs[2][64][68]  (104448 B)
// ---------------------------------------------------------------------------
#define QLD 68
#define NT (SS / 64)
#define ATTN_SMEM (26112 * 4)

__global__ void __launch_bounds__(256, 2) attn_k(const int* __restrict__ mask)
{
    extern __shared__ float sm[];
    float* Qs = sm;                   // 128*68 = 8704
    float* Ks = sm + 8704;            // 2 stages of 64*68 = 4352
    float* Vs = sm + 17408;           // 2 stages

    const int tid = threadIdx.x, lane = tid & 31, warp = tid >> 5;
    const int g = lane >> 2, tig = lane & 3;
    const int q0 = blockIdx.x * 128;
    const int h = blockIdx.y, b = blockIdx.z;
    const size_t bh = (size_t)(b * HH + h);
    const float* qb = g_q + bh * SS * HD;
    const float* kb = g_k + bh * SS * HD;
    const float* vb = g_v + bh * SS * HD;

#pragma unroll
    for (int j = 0; j < 8; j++) {
        int idx = tid + j * 256;
        int r = idx >> 4, c4 = idx & 15;
        *(float4*)&Qs[r * QLD + c4 * 4] =
            *(const float4*)(qb + (size_t)(q0 + r) * HD + c4 * 4);
    }
#pragma unroll
    for (int j = 0; j < 4; j++) {
        int idx = tid + j * 256;
        int r = idx >> 4, c4 = idx & 15;
        cpa16(&Ks[r * QLD + c4 * 4], kb + (size_t)r * HD + c4 * 4);
        cpa16(&Vs[r * QLD + c4 * 4], vb + (size_t)r * HD + c4 * 4);
    }
    CP_COMMIT();
    __syncthreads();

    const int r0 = 16 * warp + g;
    const int r1 = r0 + 8;

    float qf[8][4];
#pragma unroll
    for (int kk = 0; kk < 8; kk++) {
        qf[kk][0] = Qs[r0 * QLD + kk * 8 + tig];
        qf[kk][1] = Qs[r1 * QLD + kk * 8 + tig];
        qf[kk][2] = Qs[r0 * QLD + kk * 8 + tig + 4];
        qf[kk][3] = Qs[r1 * QLD + kk * 8 + tig + 4];
    }

    float o[8][4];
#pragma unroll
    for (int j = 0; j < 8; j++)
#pragma unroll
        for (int c = 0; c < 4; c++) o[j][c] = 0.0f;
    float mi0 = -1e30f, mi1 = -1e30f, li0 = 0.0f, li1 = 0.0f;

    const int* mrow0 = mask + ((size_t)b * SS + (q0 + r0)) * SS;
    const int* mrow1 = mask + ((size_t)b * SS + (q0 + r1)) * SS;

    const int l0 = (g << 2) | (tig >> 1);   // shfl src: P cols tig (parity tig&1)
    const int l1 = l0 + 2;                  // shfl src: P cols tig+4
    const bool odd = tig & 1;

    for (int t = 0; t < NT; t++) {
        const int st = t & 1;
        if (t + 1 < NT) {
            const float* kb2 = kb + (size_t)(t + 1) * 64 * HD;
            const float* vb2 = vb + (size_t)(t + 1) * 64 * HD;
            float* Kd = Ks + (st ^ 1) * 4352;
            float* Vd = Vs + (st ^ 1) * 4352;
#pragma unroll
            for (int j = 0; j < 4; j++) {
                int idx = tid + j * 256;
                int rr = idx >> 4, c4 = idx & 15;
                cpa16(&Kd[rr * QLD + c4 * 4], kb2 + (size_t)rr * HD + c4 * 4);
                cpa16(&Vd[rr * QLD + c4 * 4], vb2 + (size_t)rr * HD + c4 * 4);
            }
        }
        CP_COMMIT();
        CP_WAIT(1);
        __syncthreads();

        const float* Kst = Ks + st * 4352;
        const float* Vst = Vs + st * 4352;
        const int kv0 = t * 64;

        // ---- S = Q @ K^T ----
        float s[8][4];
#pragma unroll
        for (int j = 0; j < 8; j++) {
            s[j][0] = s[j][1] = s[j][2] = s[j][3] = 0.0f;
            const float* krow = &Kst[(j * 8 + g) * QLD];
#pragma unroll
            for (int kk = 0; kk < 8; kk++)
                mma8(s[j], qf[kk], krow[kk * 8 + tig], krow[kk * 8 + tig + 4]);
        }

        // ---- mask ----
#pragma unroll
        for (int j = 0; j < 8; j++) {
            int2 m0v = *(const int2*)(mrow0 + kv0 + j * 8 + 2 * tig);
            int2 m1v = *(const int2*)(mrow1 + kv0 + j * 8 + 2 * tig);
            if (m0v.x == 0) s[j][0] = -1e20f;
            if (m0v.y == 0) s[j][1] = -1e20f;
            if (m1v.x == 0) s[j][2] = -1e20f;
            if (m1v.y == 0) s[j][3] = -1e20f;
        }

        // ---- online softmax ----
        float mx0 = s[0][0], mx1 = s[0][2];
#pragma unroll
        for (int j = 0; j < 8; j++) {
            mx0 = fmaxf(mx0, fmaxf(s[j][0], s[j][1]));
            mx1 = fmaxf(mx1, fmaxf(s[j][2], s[j][3]));
        }
        mx0 = fmaxf(mx0, __shfl_xor_sync(0xffffffffu, mx0, 1));
        mx0 = fmaxf(mx0, __shfl_xor_sync(0xffffffffu, mx0, 2));
        mx1 = fmaxf(mx1, __shfl_xor_sync(0xffffffffu, mx1, 1));
        mx1 = fmaxf(mx1, __shfl_xor_sync(0xffffffffu, mx1, 2));
        const float mn0 = fmaxf(mi0, mx0), mn1 = fmaxf(mi1, mx1);
        const float a0 = __expf(mi0 - mn0), a1 = __expf(mi1 - mn1);
        float rs0 = 0.0f, rs1 = 0.0f;
#pragma unroll
        for (int j = 0; j < 8; j++) {
            s[j][0] = __expf(s[j][0] - mn0);
            s[j][1] = __expf(s[j][1] - mn0);
            s[j][2] = __expf(s[j][2] - mn1);
            s[j][3] = __expf(s[j][3] - mn1);
            rs0 += s[j][0] + s[j][1];
            rs1 += s[j][2] + s[j][3];
        }
        rs0 += __shfl_xor_sync(0xffffffffu, rs0, 1);
        rs0 += __shfl_xor_sync(0xffffffffu, rs0, 2);
        rs1 += __shfl_xor_sync(0xffffffffu, rs1, 1);
        rs1 += __shfl_xor_sync(0xffffffffu, rs1, 2);
        li0 = li0 * a0 + rs0; li1 = li1 * a1 + rs1;
        mi0 = mn0; mi1 = mn1;
#pragma unroll
        for (int j = 0; j < 8; j++) {
            o[j][0] *= a0; o[j][1] *= a0;
            o[j][2] *= a1; o[j][3] *= a1;
            // tf32 RN for the PV mma inputs
            s[j][0] = wmma::__float_to_tf32(s[j][0]);
            s[j][1] = wmma::__float_to_tf32(s[j][1]);
            s[j][2] = wmma::__float_to_tf32(s[j][2]);
            s[j][3] = wmma::__float_to_tf32(s[j][3]);
        }

        // ---- O += P @ V ; P A-frags gathered via shfl from S D-frags ----
        // P[r0][kk*8+c] lives in lane (g<<2)|(c>>1), reg s[kk][c&1] (r0) /
        // s[kk][2+(c&1)] (r1). Need c = tig (pa0/pa1) and c = tig+4 (pa2/pa3).
#pragma unroll
        for (int kk = 0; kk < 8; kk++) {
            float u0 = __shfl_sync(0xffffffffu, s[kk][0], l0);
            float u1 = __shfl_sync(0xffffffffu, s[kk][1], l0);
            float u2 = __shfl_sync(0xffffffffu, s[kk][2], l0);
            float u3 = __shfl_sync(0xffffffffu, s[kk][3], l0);
            float w0 = __shfl_sync(0xffffffffu, s[kk][0], l1);
            float w1 = __shfl_sync(0xffffffffu, s[kk][1], l1);
            float w2 = __shfl_sync(0xffffffffu, s[kk][2], l1);
            float w3 = __shfl_sync(0xffffffffu, s[kk][3], l1);
            float pa[4];
            pa[0] = odd ? u1 : u0;   // P[r0][kk*8+tig]
            pa[1] = odd ? u3 : u2;   // P[r1][kk*8+tig]
            pa[2] = odd ? w1 : w0;   // P[r0][kk*8+tig+4]
            pa[3] = odd ? w3 : w2;   // P[r1][kk*8+tig+4]
            const float* v0 = &Vst[(kk * 8 + tig) * QLD];
            const float* v1 = &Vst[(kk * 8 + tig + 4) * QLD];
#pragma unroll
            for (int j = 0; j < 8; j++)
                mma8(o[j], pa, v0[j * 8 + g], v1[j * 8 + g]);
        }
        __syncthreads();
    }

    const float inv0 = 1.0f / li0, inv1 = 1.0f / li1;
    float* dst0 = g_ao + ((size_t)b * SS + (q0 + r0)) * DD + h * HD;
    float* dst1 = g_ao + ((size_t)b * SS + (q0 + r1)) * DD + h * HD;
#pragma unroll
    for (int j = 0; j < 8; j++) {
        float2 w0 = make_float2(wmma::__float_to_tf32(o[j][0] * inv0),
                                wmma::__float_to_tf32(o[j][1] * inv0));
        float2 w1 = make_float2(wmma::__float_to_tf32(o[j][2] * inv1),
                                wmma::__float_to_tf32(o[j][3] * inv1));
        *(float2*)&dst0[j * 8 + 2 * tig] = w0;
        *(float2*)&dst1[j * 8 + 2 * tig] = w1;
    }
}

// ---------------------------------------------------------------------------
extern "C" void kernel_launch(void* const* d_in, const int* in_sizes, int n_in,
                              void* d_out, int out_size)
{
    const float* x    = (const float*)d_in[0];
    const int*   mask = (const int*)  d_in[1];
    const float* Wqkv = (const float*)d_in[2];
    const float* bqkv = (const float*)d_in[3];
    const float* Wo   = (const float*)d_in[4];
    const float* bo   = (const float*)d_in[5];
    float* out = (float*)d_out;
    (void)in_sizes; (void)n_in; (void)out_size;

    cudaFuncSetAttribute(attn_k, cudaFuncAttributeMaxDynamicSharedMemorySize,
                         ATTN_SMEM);
    cudaFuncSetAttribute(mgemm_k<0>, cudaFuncAttributeMaxDynamicSharedMemorySize,
                         GSMEM);
    cudaFuncSetAttribute(mgemm_k<1>, cudaFuncAttributeMaxDynamicSharedMemorySize,
                         GSMEM);

    // 0) tf32 RN pre-round of raw inputs
    round_k<<<(BB * SS * DD / 4 + 255) / 256, 256>>>((const float4*)x, 0,
                                                     BB * SS * DD / 4);
    round_k<<<(3 * DD * DD / 4 + 255) / 256, 256>>>((const float4*)Wqkv, 1,
                                                    3 * DD * DD / 4);
    round_k<<<(DD * DD / 4 + 255) / 256, 256>>>((const float4*)Wo, 2,
                                                DD * DD / 4);

    // 1) QKV projection -> q/k/v (tf32-rounded, q pre-scaled)
    {
        dim3 grid(3 * DD / 128, (BB * SS) / 128);
        mgemm_k<0><<<grid, 256, GSMEM>>>(bqkv, nullptr, 3 * DD, DD);
    }

    // 2) Flash attention (mma.sync tf32) -> g_ao
    attn_k<<<dim3(SS / 128, HH, BB), 256, ATTN_SMEM>>>(mask);

    // 3) Output projection -> d_out (fp32)
    {
        dim3 grid(DD / 128, (BB * SS) / 128);
        mgemm_k<1><<<grid, 256, GSMEM>>>(bo, out, DD, DD);
    }
}

// round 7
// speedup vs baseline: 2.9883x; 1.0424x over previous
#include <cuda_runtime.h>
#include <mma.h>
#include <cstdint>

using namespace nvcuda;

#define BB 4
#define SS 1024
#define DD 1024
#define HH 16
#define HD 64

// Scratch (__device__ globals — allocation-free rule)
static __device__ float g_q[BB * HH * SS * HD];
static __device__ float g_k[BB * HH * SS * HD];
static __device__ float g_v[BB * HH * SS * HD];
static __device__ float g_ao[BB * SS * DD];
static __device__ float g_xr[BB * SS * DD];      // tf32-rounded x
static __device__ float g_wqkvr[DD * 3 * DD];    // tf32-rounded Wqkv [K][N]
static __device__ float g_wor[DD * DD];          // tf32-rounded Wo   [K][N]

__device__ __forceinline__ void cpa16(void* dst, const void* src) {
    unsigned d = (unsigned)__cvta_generic_to_shared(dst);
    asm volatile("cp.async.cg.shared.global [%0], [%1], 16;\n" :: "r"(d), "l"(src));
}
#define CP_COMMIT() asm volatile("cp.async.commit_group;\n" ::)
#define CP_WAIT(N)  asm volatile("cp.async.wait_group %0;\n" :: "n"(N))

// m16n8k8 tf32 mma (A row-major, B col-major), D/C fp32, accumulate in place
__device__ __forceinline__ void mma8(float* d, const float* a,
                                     float b0, float b1) {
    asm volatile(
        "mma.sync.aligned.m16n8k8.row.col.f32.tf32.tf32.f32 "
        "{%0,%1,%2,%3}, {%4,%5,%6,%7}, {%8,%9}, {%0,%1,%2,%3};"
        : "+f"(d[0]), "+f"(d[1]), "+f"(d[2]), "+f"(d[3])
        : "r"(__float_as_uint(a[0])), "r"(__float_as_uint(a[1])),
          "r"(__float_as_uint(a[2])), "r"(__float_as_uint(a[3])),
          "r"(__float_as_uint(b0)), "r"(__float_as_uint(b1)));
}

// ---------------------------------------------------------------------------
// tf32 RN pre-round pass
// ---------------------------------------------------------------------------
__global__ void round_k(const float4* __restrict__ src, int which, int n4) {
    float4* dst = which == 0 ? (float4*)g_xr
                : which == 1 ? (float4*)g_wqkvr : (float4*)g_wor;
    int i = blockIdx.x * blockDim.x + threadIdx.x;
    if (i < n4) {
        float4 v = src[i];
        v.x = wmma::__float_to_tf32(v.x);
        v.y = wmma::__float_to_tf32(v.y);
        v.z = wmma::__float_to_tf32(v.z);
        v.w = wmma::__float_to_tf32(v.w);
        dst[i] = v;
    }
}

// ---------------------------------------------------------------------------
// Raw mma.sync tf32 GEMM. CTA tile 128x128, BK=32, 256 thr (8 warps 2x4,
// warp tile 64x32). 3-stage cp.async ring, ONE barrier per slab, loads
// issued right after the barrier (full slab of latency cover).
// Stage: A[128][36] (4608 f) + B[32][136] (4352 f) = 8960 f = 35840 B.
// ---------------------------------------------------------------------------
#define GSTG 8960
#define GSMEM (3 * GSTG * 4)

template <int MODE>
__global__ void __launch_bounds__(256, 2) mgemm_k(
    const float* __restrict__ bias, float* __restrict__ C, int N, int K)
{
    extern __shared__ float sm[];

    const int tid = threadIdx.x, lane = tid & 31, warp = tid >> 5;
    const int g = lane >> 2, tig = lane & 3;
    const int wm = (warp >> 2) * 64, wn = (warp & 3) * 32;
    const int m0 = blockIdx.y * 128, n0 = blockIdx.x * 128;

    const float* Ap = (MODE == 0) ? (const float*)g_xr    : (const float*)g_ao;
    const float* Bp = (MODE == 0) ? (const float*)g_wqkvr : (const float*)g_wor;

    // A: 128x32 = 1024 float4, 4/thread (row = id>>3, c = id&7)
    // B: 32x128 = 1024 float4, 4/thread (row = id>>5, col = id&31)
    const int ar = tid >> 3, ac = (tid & 7) * 4;
    const int br = tid >> 5, bc = (tid & 31) * 4;

    auto issue = [&](int st, int k0) {
        float* As = sm + st * GSTG;
        float* Bs = As + 4608;
#pragma unroll
        for (int v = 0; v < 4; v++)
            cpa16(&As[(ar + v * 32) * 36 + ac],
                  Ap + (size_t)(m0 + ar + v * 32) * K + k0 + ac);
#pragma unroll
        for (int v = 0; v < 4; v++)
            cpa16(&Bs[(br + v * 8) * 136 + bc],
                  Bp + (size_t)(k0 + br + v * 8) * N + n0 + bc);
    };

    float d[4][4][4];
#pragma unroll
    for (int mf = 0; mf < 4; mf++)
#pragma unroll
        for (int nf = 0; nf < 4; nf++)
#pragma unroll
            for (int c = 0; c < 4; c++) d[mf][nf][c] = 0.0f;

    issue(0, 0);  CP_COMMIT();
    issue(1, 32); CP_COMMIT();

    const int NI = K / 32;
    for (int i = 0; i < NI; i++) {
        const int st = i % 3;
        CP_WAIT(1);
        __syncthreads();
        if (i + 2 < NI) issue((i + 2) % 3, (i + 2) * 32);
        CP_COMMIT();

        const float* As = sm + st * GSTG;
        const float* Bs = As + 4608;

        // double-buffered frag loads over 4 k-steps
        float af[2][4][4], bf[2][4][2];
        auto ldA = [&](int buf, int kk) {
#pragma unroll
            for (int mf = 0; mf < 4; mf++) {
                const float* a0 = &As[(wm + mf * 16 + g) * 36 + kk * 8 + tig];
                const float* a1 = &As[(wm + mf * 16 + g + 8) * 36 + kk * 8 + tig];
                af[buf][mf][0] = a0[0]; af[buf][mf][1] = a1[0];
                af[buf][mf][2] = a0[4]; af[buf][mf][3] = a1[4];
            }
        };
        auto ldB = [&](int buf, int kk) {
#pragma unroll
            for (int nf = 0; nf < 4; nf++) {
                bf[buf][nf][0] = Bs[(kk * 8 + tig) * 136 + wn + nf * 8 + g];
                bf[buf][nf][1] = Bs[(kk * 8 + tig + 4) * 136 + wn + nf * 8 + g];
            }
        };
        ldA(0, 0); ldB(0, 0);
#pragma unroll
        for (int kk = 0; kk < 4; kk++) {
            const int cur = kk & 1;
            if (kk < 3) { ldA(cur ^ 1, kk + 1); ldB(cur ^ 1, kk + 1); }
#pragma unroll
            for (int mf = 0; mf < 4; mf++)
#pragma unroll
                for (int nf = 0; nf < 4; nf++)
                    mma8(d[mf][nf], af[cur][mf], bf[cur][nf][0], bf[cur][nf][1]);
        }
    }

    // ---- direct epilogue (D-frag: rows g,g+8; cols 2tig,2tig+1) ----
#pragma unroll
    for (int mf = 0; mf < 4; mf++) {
        const int m = m0 + wm + mf * 16 + g;
        const int bb = m >> 10, srow = m & 1023;
#pragma unroll
        for (int nf = 0; nf < 4; nf++) {
            const int col0 = n0 + wn + nf * 8 + 2 * tig;
            const float b0 = bias[col0], b1 = bias[col0 + 1];
            float v0 = d[mf][nf][0] + b0, v1 = d[mf][nf][1] + b1;
            float v2 = d[mf][nf][2] + b0, v3 = d[mf][nf][3] + b1;

            if (MODE == 0) {
                const int h = col0 / 192;
                const int rr = col0 - h * 192;
                const int seg = rr >> 6;
                const int db = rr & 63;
                const size_t idx =
                    (((size_t)(bb * HH + h)) * SS + srow) * HD + db;
                float* dst = (seg == 0) ? g_q : (seg == 1) ? g_k : g_v;
                const float sc = (seg == 0) ? 0.125f : 1.0f;
                float2 w0 = make_float2(wmma::__float_to_tf32(v0 * sc),
                                        wmma::__float_to_tf32(v1 * sc));
                float2 w1 = make_float2(wmma::__float_to_tf32(v2 * sc),
                                        wmma::__float_to_tf32(v3 * sc));
                *(float2*)&dst[idx]           = w0;
                *(float2*)&dst[idx + 8 * HD]  = w1;
            } else {
                float* dst = C + (size_t)m * N + col0;
                *(float2*)dst           = make_float2(v0, v1);
                *(float2*)(dst + 8 * N) = make_float2(v2, v3);
            }
        }
    }
}

// ---------------------------------------------------------------------------
// Flash attention FA2 on mma.sync tf32, register-resident, shfl P transport.
// smem floats: Qs[128][68] | Ks[2][64][68] | Vs[2][64][68]  (104448 B)
// ---------------------------------------------------------------------------
#define QLD 68
#define NT (SS / 64)
#define ATTN_SMEM (26112 * 4)

__global__ void __launch_bounds__(256, 2) attn_k(const int* __restrict__ mask)
{
    extern __shared__ float sm[];
    float* Qs = sm;                   // 128*68 = 8704
    float* Ks = sm + 8704;            // 2 stages of 64*68 = 4352
    float* Vs = sm + 17408;           // 2 stages

    const int tid = threadIdx.x, lane = tid & 31, warp = tid >> 5;
    const int g = lane >> 2, tig = lane & 3;
    const int q0 = blockIdx.x * 128;
    const int h = blockIdx.y, b = blockIdx.z;
    const size_t bh = (size_t)(b * HH + h);
    const float* qb = g_q + bh * SS * HD;
    const float* kb = g_k + bh * SS * HD;
    const float* vb = g_v + bh * SS * HD;

#pragma unroll
    for (int j = 0; j < 8; j++) {
        int idx = tid + j * 256;
        int r = idx >> 4, c4 = idx & 15;
        *(float4*)&Qs[r * QLD + c4 * 4] =
            *(const float4*)(qb + (size_t)(q0 + r) * HD + c4 * 4);
    }
#pragma unroll
    for (int j = 0; j < 4; j++) {
        int idx = tid + j * 256;
        int r = idx >> 4, c4 = idx & 15;
        cpa16(&Ks[r * QLD + c4 * 4], kb + (size_t)r * HD + c4 * 4);
        cpa16(&Vs[r * QLD + c4 * 4], vb + (size_t)r * HD + c4 * 4);
    }
    CP_COMMIT();
    __syncthreads();

    const int r0 = 16 * warp + g;
    const int r1 = r0 + 8;

    float qf[8][4];
#pragma unroll
    for (int kk = 0; kk < 8; kk++) {
        qf[kk][0] = Qs[r0 * QLD + kk * 8 + tig];
        qf[kk][1] = Qs[r1 * QLD + kk * 8 + tig];
        qf[kk][2] = Qs[r0 * QLD + kk * 8 + tig + 4];
        qf[kk][3] = Qs[r1 * QLD + kk * 8 + tig + 4];
    }

    float o[8][4];
#pragma unroll
    for (int j = 0; j < 8; j++)
#pragma unroll
        for (int c = 0; c < 4; c++) o[j][c] = 0.0f;
    float mi0 = -1e30f, mi1 = -1e30f, li0 = 0.0f, li1 = 0.0f;

    const int* mrow0 = mask + ((size_t)b * SS + (q0 + r0)) * SS;
    const int* mrow1 = mask + ((size_t)b * SS + (q0 + r1)) * SS;

    const int l0 = (g << 2) | (tig >> 1);
    const int l1 = l0 + 2;
    const bool odd = tig & 1;

    for (int t = 0; t < NT; t++) {
        const int st = t & 1;
        if (t + 1 < NT) {
            const float* kb2 = kb + (size_t)(t + 1) * 64 * HD;
            const float* vb2 = vb + (size_t)(t + 1) * 64 * HD;
            float* Kd = Ks + (st ^ 1) * 4352;
            float* Vd = Vs + (st ^ 1) * 4352;
#pragma unroll
            for (int j = 0; j < 4; j++) {
                int idx = tid + j * 256;
                int rr = idx >> 4, c4 = idx & 15;
                cpa16(&Kd[rr * QLD + c4 * 4], kb2 + (size_t)rr * HD + c4 * 4);
                cpa16(&Vd[rr * QLD + c4 * 4], vb2 + (size_t)rr * HD + c4 * 4);
            }
        }
        CP_COMMIT();

        // prefetch mask (latency hides under the S MMAs below)
        const int kv0 = t * 64;
        int2 mv0[8], mv1[8];
#pragma unroll
        for (int j = 0; j < 8; j++) {
            mv0[j] = *(const int2*)(mrow0 + kv0 + j * 8 + 2 * tig);
            mv1[j] = *(const int2*)(mrow1 + kv0 + j * 8 + 2 * tig);
        }

        CP_WAIT(1);
        __syncthreads();

        const float* Kst = Ks + st * 4352;
        const float* Vst = Vs + st * 4352;

        // ---- S = Q @ K^T ----
        float s[8][4];
#pragma unroll
        for (int j = 0; j < 8; j++) {
            s[j][0] = s[j][1] = s[j][2] = s[j][3] = 0.0f;
            const float* krow = &Kst[(j * 8 + g) * QLD];
#pragma unroll
            for (int kk = 0; kk < 8; kk++)
                mma8(s[j], qf[kk], krow[kk * 8 + tig], krow[kk * 8 + tig + 4]);
        }

        // ---- mask (registers already loaded) ----
#pragma unroll
        for (int j = 0; j < 8; j++) {
            if (mv0[j].x == 0) s[j][0] = -1e20f;
            if (mv0[j].y == 0) s[j][1] = -1e20f;
            if (mv1[j].x == 0) s[j][2] = -1e20f;
            if (mv1[j].y == 0) s[j][3] = -1e20f;
        }

        // ---- online softmax ----
        float mx0 = s[0][0], mx1 = s[0][2];
#pragma unroll
        for (int j = 0; j < 8; j++) {
            mx0 = fmaxf(mx0, fmaxf(s[j][0], s[j][1]));
            mx1 = fmaxf(mx1, fmaxf(s[j][2], s[j][3]));
        }
        mx0 = fmaxf(mx0, __shfl_xor_sync(0xffffffffu, mx0, 1));
        mx0 = fmaxf(mx0, __shfl_xor_sync(0xffffffffu, mx0, 2));
        mx1 = fmaxf(mx1, __shfl_xor_sync(0xffffffffu, mx1, 1));
        mx1 = fmaxf(mx1, __shfl_xor_sync(0xffffffffu, mx1, 2));
        const float mn0 = fmaxf(mi0, mx0), mn1 = fmaxf(mi1, mx1);
        const float a0 = __expf(mi0 - mn0), a1 = __expf(mi1 - mn1);
        float rs0 = 0.0f, rs1 = 0.0f;
#pragma unroll
        for (int j = 0; j < 8; j++) {
            s[j][0] = __expf(s[j][0] - mn0);
            s[j][1] = __expf(s[j][1] - mn0);
            s[j][2] = __expf(s[j][2] - mn1);
            s[j][3] = __expf(s[j][3] - mn1);
            rs0 += s[j][0] + s[j][1];
            rs1 += s[j][2] + s[j][3];
        }
        rs0 += __shfl_xor_sync(0xffffffffu, rs0, 1);
        rs0 += __shfl_xor_sync(0xffffffffu, rs0, 2);
        rs1 += __shfl_xor_sync(0xffffffffu, rs1, 1);
        rs1 += __shfl_xor_sync(0xffffffffu, rs1, 2);
        li0 = li0 * a0 + rs0; li1 = li1 * a1 + rs1;
        mi0 = mn0; mi1 = mn1;
#pragma unroll
        for (int j = 0; j < 8; j++) {
            o[j][0] *= a0; o[j][1] *= a0;
            o[j][2] *= a1; o[j][3] *= a1;
            s[j][0] = wmma::__float_to_tf32(s[j][0]);
            s[j][1] = wmma::__float_to_tf32(s[j][1]);
            s[j][2] = wmma::__float_to_tf32(s[j][2]);
            s[j][3] = wmma::__float_to_tf32(s[j][3]);
        }

        // ---- O += P @ V ; P A-frags via shfl ----
#pragma unroll
        for (int kk = 0; kk < 8; kk++) {
            float u0 = __shfl_sync(0xffffffffu, s[kk][0], l0);
            float u1 = __shfl_sync(0xffffffffu, s[kk][1], l0);
            float u2 = __shfl_sync(0xffffffffu, s[kk][2], l0);
            float u3 = __shfl_sync(0xffffffffu, s[kk][3], l0);
            float w0 = __shfl_sync(0xffffffffu, s[kk][0], l1);
            float w1 = __shfl_sync(0xffffffffu, s[kk][1], l1);
            float w2 = __shfl_sync(0xffffffffu, s[kk][2], l1);
            float w3 = __shfl_sync(0xffffffffu, s[kk][3], l1);
            float pa[4];
            pa[0] = odd ? u1 : u0;
            pa[1] = odd ? u3 : u2;
            pa[2] = odd ? w1 : w0;
            pa[3] = odd ? w3 : w2;
            const float* v0 = &Vst[(kk * 8 + tig) * QLD];
            const float* v1 = &Vst[(kk * 8 + tig + 4) * QLD];
#pragma unroll
            for (int j = 0; j < 8; j++)
                mma8(o[j], pa, v0[j * 8 + g], v1[j * 8 + g]);
        }
        __syncthreads();
    }

    const float inv0 = 1.0f / li0, inv1 = 1.0f / li1;
    float* dst0 = g_ao + ((size_t)b * SS + (q0 + r0)) * DD + h * HD;
    float* dst1 = g_ao + ((size_t)b * SS + (q0 + r1)) * DD + h * HD;
#pragma unroll
    for (int j = 0; j < 8; j++) {
        float2 w0 = make_float2(wmma::__float_to_tf32(o[j][0] * inv0),
                                wmma::__float_to_tf32(o[j][1] * inv0));
        float2 w1 = make_float2(wmma::__float_to_tf32(o[j][2] * inv1),
                                wmma::__float_to_tf32(o[j][3] * inv1));
        *(float2*)&dst0[j * 8 + 2 * tig] = w0;
        *(float2*)&dst1[j * 8 + 2 * tig] = w1;
    }
}

// ---------------------------------------------------------------------------
extern "C" void kernel_launch(void* const* d_in, const int* in_sizes, int n_in,
                              void* d_out, int out_size)
{
    const float* x    = (const float*)d_in[0];
    const int*   mask = (const int*)  d_in[1];
    const float* Wqkv = (const float*)d_in[2];
    const float* bqkv = (const float*)d_in[3];
    const float* Wo   = (const float*)d_in[4];
    const float* bo   = (const float*)d_in[5];
    float* out = (float*)d_out;
    (void)in_sizes; (void)n_in; (void)out_size;

    cudaFuncSetAttribute(attn_k, cudaFuncAttributeMaxDynamicSharedMemorySize,
                         ATTN_SMEM);
    cudaFuncSetAttribute(mgemm_k<0>, cudaFuncAttributeMaxDynamicSharedMemorySize,
                         GSMEM);
    cudaFuncSetAttribute(mgemm_k<1>, cudaFuncAttributeMaxDynamicSharedMemorySize,
                         GSMEM);

    // 0) tf32 RN pre-round of raw inputs
    round_k<<<(BB * SS * DD / 4 + 255) / 256, 256>>>((const float4*)x, 0,
                                                     BB * SS * DD / 4);
    round_k<<<(3 * DD * DD / 4 + 255) / 256, 256>>>((const float4*)Wqkv, 1,
                                                    3 * DD * DD / 4);
    round_k<<<(DD * DD / 4 + 255) / 256, 256>>>((const float4*)Wo, 2,
                                                DD * DD / 4);

    // 1) QKV projection -> q/k/v (tf32-rounded, q pre-scaled)
    {
        dim3 grid(3 * DD / 128, (BB * SS) / 128);
        mgemm_k<0><<<grid, 256, GSMEM>>>(bqkv, nullptr, 3 * DD, DD);
    }

    // 2) Flash attention (mma.sync tf32) -> g_ao
    attn_k<<<dim3(SS / 128, HH, BB), 256, ATTN_SMEM>>>(mask);

    // 3) Output projection -> d_out (fp32)
    {
        dim3 grid(DD / 128, (BB * SS) / 128);
        mgemm_k<1><<<grid, 256, GSMEM>>>(bo, out, DD, DD);
    }
}

// round 8
// speedup vs baseline: 3.4605x; 1.1580x over previous
#include <cuda_runtime.h>
#include <mma.h>
#include <cstdint>

using namespace nvcuda;

#define BB 4
#define SS 1024
#define DD 1024
#define HH 16
#define HD 64

// Scratch (__device__ globals — allocation-free rule)
static __device__ float g_q[BB * HH * SS * HD];
static __device__ float g_k[BB * HH * SS * HD];
static __device__ float g_v[BB * HH * SS * HD];
static __device__ float g_ao[BB * SS * DD];
static __device__ float g_xr[BB * SS * DD];       // tf32-rounded x
static __device__ float g_wqkvr[DD * 3 * DD];     // tf32-rounded Wqkv [K][N]
static __device__ float g_wor[DD * DD];           // tf32-rounded Wo   [K][N]
static __device__ uint32_t g_mb[BB * SS * (SS / 32)];  // packed mask bits

__device__ __forceinline__ void cpa16(void* dst, const void* src) {
    unsigned d = (unsigned)__cvta_generic_to_shared(dst);
    asm volatile("cp.async.cg.shared.global [%0], [%1], 16;\n" :: "r"(d), "l"(src));
}
#define CP_COMMIT() asm volatile("cp.async.commit_group;\n" ::)
#define CP_WAIT(N)  asm volatile("cp.async.wait_group %0;\n" :: "n"(N))

// m16n8k8 tf32 mma (A row-major, B col-major), D/C fp32, accumulate in place
__device__ __forceinline__ void mma8(float* d, const float* a,
                                     float b0, float b1) {
    asm volatile(
        "mma.sync.aligned.m16n8k8.row.col.f32.tf32.tf32.f32 "
        "{%0,%1,%2,%3}, {%4,%5,%6,%7}, {%8,%9}, {%0,%1,%2,%3};"
        : "+f"(d[0]), "+f"(d[1]), "+f"(d[2]), "+f"(d[3])
        : "r"(__float_as_uint(a[0])), "r"(__float_as_uint(a[1])),
          "r"(__float_as_uint(a[2])), "r"(__float_as_uint(a[3])),
          "r"(__float_as_uint(b0)), "r"(__float_as_uint(b1)));
}

// ---------------------------------------------------------------------------
// Pre-passes
// ---------------------------------------------------------------------------
__global__ void round_k(const float4* __restrict__ src, int which, int n4) {
    float4* dst = which == 0 ? (float4*)g_xr
                : which == 1 ? (float4*)g_wqkvr : (float4*)g_wor;
    int i = blockIdx.x * blockDim.x + threadIdx.x;
    if (i < n4) {
        float4 v = src[i];
        v.x = wmma::__float_to_tf32(v.x);
        v.y = wmma::__float_to_tf32(v.y);
        v.z = wmma::__float_to_tf32(v.z);
        v.w = wmma::__float_to_tf32(v.w);
        dst[i] = v;
    }
}

// pack 32 mask ints into one bit word; idx = (b*SS+q)*32 + w
__global__ void maskpack_k(const int* __restrict__ mask) {
    int idx = blockIdx.x * 256 + threadIdx.x;
    if (idx >= BB * SS * (SS / 32)) return;
    const int4* src = (const int4*)(mask + (size_t)idx * 32);
    uint32_t w = 0;
#pragma unroll
    for (int i = 0; i < 8; i++) {
        int4 v = src[i];
        w |= (v.x != 0 ? 1u : 0u) << (i * 4 + 0);
        w |= (v.y != 0 ? 1u : 0u) << (i * 4 + 1);
        w |= (v.z != 0 ? 1u : 0u) << (i * 4 + 2);
        w |= (v.w != 0 ? 1u : 0u) << (i * 4 + 3);
    }
    g_mb[idx] = w;
}

// ---------------------------------------------------------------------------
// Raw mma.sync tf32 GEMM. CTA tile 128x128, BK=32, 128 thr (4 warps 2x2,
// warp tile 64x64). 3-stage cp.async ring, one barrier per slab.
// Stage: A[128][36] (4608 f) + B[32][136] (4352 f) = 8960 f.
// ---------------------------------------------------------------------------
#define GSTG 8960
#define GSMEM (3 * GSTG * 4)

template <int MODE>
__global__ void __launch_bounds__(128, 2) mgemm_k(
    const float* __restrict__ bias, float* __restrict__ C, int N, int K)
{
    extern __shared__ float sm[];

    const int tid = threadIdx.x, lane = tid & 31, warp = tid >> 5;
    const int g = lane >> 2, tig = lane & 3;
    const int wm = (warp >> 1) * 64, wn = (warp & 1) * 64;
    const int m0 = blockIdx.y * 128, n0 = blockIdx.x * 128;

    const float* Ap = (MODE == 0) ? (const float*)g_xr    : (const float*)g_ao;
    const float* Bp = (MODE == 0) ? (const float*)g_wqkvr : (const float*)g_wor;

    // A: 128x32 = 1024 float4, 8/thread; B: 32x128(+pad) = 1024 float4, 8/thread
    const int ar = tid >> 3, ac = (tid & 7) * 4;    // rows ar + v*16
    const int br = tid >> 5, bc = (tid & 31) * 4;   // rows br + v*4

    auto issue = [&](int st, int k0) {
        float* As = sm + st * GSTG;
        float* Bs = As + 4608;
#pragma unroll
        for (int v = 0; v < 8; v++)
            cpa16(&As[(ar + v * 16) * 36 + ac],
                  Ap + (size_t)(m0 + ar + v * 16) * K + k0 + ac);
#pragma unroll
        for (int v = 0; v < 8; v++)
            cpa16(&Bs[(br + v * 4) * 136 + bc],
                  Bp + (size_t)(k0 + br + v * 4) * N + n0 + bc);
    };

    float d[4][8][4];
#pragma unroll
    for (int mf = 0; mf < 4; mf++)
#pragma unroll
        for (int nf = 0; nf < 8; nf++)
#pragma unroll
            for (int c = 0; c < 4; c++) d[mf][nf][c] = 0.0f;

    issue(0, 0);  CP_COMMIT();
    issue(1, 32); CP_COMMIT();

    const int NI = K / 32;
    for (int i = 0; i < NI; i++) {
        const int st = i % 3;
        CP_WAIT(1);
        __syncthreads();
        if (i + 2 < NI) issue((i + 2) % 3, (i + 2) * 32);
        CP_COMMIT();

        const float* As = sm + st * GSTG;
        const float* Bs = As + 4608;

        float af[2][4][4], bf[2][8][2];
        auto ldA = [&](int buf, int kk) {
#pragma unroll
            for (int mf = 0; mf < 4; mf++) {
                const float* a0 = &As[(wm + mf * 16 + g) * 36 + kk * 8 + tig];
                const float* a1 = &As[(wm + mf * 16 + g + 8) * 36 + kk * 8 + tig];
                af[buf][mf][0] = a0[0]; af[buf][mf][1] = a1[0];
                af[buf][mf][2] = a0[4]; af[buf][mf][3] = a1[4];
            }
        };
        auto ldB = [&](int buf, int kk) {
#pragma unroll
            for (int nf = 0; nf < 8; nf++) {
                bf[buf][nf][0] = Bs[(kk * 8 + tig) * 136 + wn + nf * 8 + g];
                bf[buf][nf][1] = Bs[(kk * 8 + tig + 4) * 136 + wn + nf * 8 + g];
            }
        };
        ldA(0, 0); ldB(0, 0);
#pragma unroll
        for (int kk = 0; kk < 4; kk++) {
            const int cur = kk & 1;
            if (kk < 3) { ldA(cur ^ 1, kk + 1); ldB(cur ^ 1, kk + 1); }
#pragma unroll
            for (int mf = 0; mf < 4; mf++)
#pragma unroll
                for (int nf = 0; nf < 8; nf++)
                    mma8(d[mf][nf], af[cur][mf], bf[cur][nf][0], bf[cur][nf][1]);
        }
    }

    // ---- direct epilogue ----
#pragma unroll
    for (int mf = 0; mf < 4; mf++) {
        const int m = m0 + wm + mf * 16 + g;
        const int bb = m >> 10, srow = m & 1023;
#pragma unroll
        for (int nf = 0; nf < 8; nf++) {
            const int col0 = n0 + wn + nf * 8 + 2 * tig;
            const float b0 = bias[col0], b1 = bias[col0 + 1];
            float v0 = d[mf][nf][0] + b0, v1 = d[mf][nf][1] + b1;
            float v2 = d[mf][nf][2] + b0, v3 = d[mf][nf][3] + b1;

            if (MODE == 0) {
                const int h = col0 / 192;
                const int rr = col0 - h * 192;
                const int seg = rr >> 6;
                const int db = rr & 63;
                const size_t idx =
                    (((size_t)(bb * HH + h)) * SS + srow) * HD + db;
                float* dst = (seg == 0) ? g_q : (seg == 1) ? g_k : g_v;
                const float sc = (seg == 0) ? 0.125f : 1.0f;
                float2 w0 = make_float2(wmma::__float_to_tf32(v0 * sc),
                                        wmma::__float_to_tf32(v1 * sc));
                float2 w1 = make_float2(wmma::__float_to_tf32(v2 * sc),
                                        wmma::__float_to_tf32(v3 * sc));
                *(float2*)&dst[idx]          = w0;
                *(float2*)&dst[idx + 8 * HD] = w1;
            } else {
                float* dst = C + (size_t)m * N + col0;
                *(float2*)dst           = make_float2(v0, v1);
                *(float2*)(dst + 8 * N) = make_float2(v2, v3);
            }
        }
    }
}

// ---------------------------------------------------------------------------
// Flash attention FA2, mma.sync tf32. 128 thr (4 warps), q-block 128,
// warp q-tile 32 (2 m-frags). K pad 68, V pad 72 (both conflict-free).
// Bitmask masking from g_mb. shfl P transport, register O.
// smem floats: Qs[128][68]=8704 | Ks[2][64][68]=8704 | Vs[2][64][72]=9216
// ---------------------------------------------------------------------------
#define KLD 68
#define VLD 72
#define NT (SS / 64)
#define ATTN_SMEM (26624 * 4)

__global__ void __launch_bounds__(128, 2) attn_k(void)
{
    extern __shared__ float sm[];
    float* Qs = sm;
    float* Ks = sm + 8704;    // stage stride 4352
    float* Vs = sm + 17408;   // stage stride 4608

    const int tid = threadIdx.x, lane = tid & 31, warp = tid >> 5;
    const int g = lane >> 2, tig = lane & 3;
    const int q0 = blockIdx.x * 128;
    const int h = blockIdx.y, b = blockIdx.z;
    const size_t bh = (size_t)(b * HH + h);
    const float* qb = g_q + bh * SS * HD;
    const float* kb = g_k + bh * SS * HD;
    const float* vb = g_v + bh * SS * HD;

    // Q tile -> smem
#pragma unroll
    for (int j = 0; j < 16; j++) {
        int idx = tid + j * 128;
        int r = idx >> 4, c4 = idx & 15;
        *(float4*)&Qs[r * KLD + c4 * 4] =
            *(const float4*)(qb + (size_t)(q0 + r) * HD + c4 * 4);
    }
    // prefetch KV tile 0
#pragma unroll
    for (int j = 0; j < 8; j++) {
        int idx = tid + j * 128;
        int r = idx >> 4, c4 = idx & 15;
        cpa16(&Ks[r * KLD + c4 * 4], kb + (size_t)r * HD + c4 * 4);
        cpa16(&Vs[r * VLD + c4 * 4], vb + (size_t)r * HD + c4 * 4);
    }
    CP_COMMIT();
    __syncthreads();

    // warp owns q rows [32*warp, 32*warp+32): 2 m-frags
    const int rb = 32 * warp;
    float qf[2][8][4];
#pragma unroll
    for (int mf = 0; mf < 2; mf++) {
        const int r0 = rb + mf * 16 + g, r1 = r0 + 8;
#pragma unroll
        for (int kk = 0; kk < 8; kk++) {
            qf[mf][kk][0] = Qs[r0 * KLD + kk * 8 + tig];
            qf[mf][kk][1] = Qs[r1 * KLD + kk * 8 + tig];
            qf[mf][kk][2] = Qs[r0 * KLD + kk * 8 + tig + 4];
            qf[mf][kk][3] = Qs[r1 * KLD + kk * 8 + tig + 4];
        }
    }

    float o[2][8][4];
#pragma unroll
    for (int mf = 0; mf < 2; mf++)
#pragma unroll
        for (int j = 0; j < 8; j++)
#pragma unroll
            for (int c = 0; c < 4; c++) o[mf][j][c] = 0.0f;
    float mi[2][2], li[2][2];
#pragma unroll
    for (int mf = 0; mf < 2; mf++) {
        mi[mf][0] = mi[mf][1] = -1e30f;
        li[mf][0] = li[mf][1] = 0.0f;
    }

    // bitmask row pointers (words of 32 cols)
    const uint32_t* mb0 = g_mb + ((size_t)b * SS + (q0 + rb + g)) * 32;       // mf0 r0
    const uint32_t* mb1 = g_mb + ((size_t)b * SS + (q0 + rb + g + 8)) * 32;   // mf0 r1
    const uint32_t* mb2 = g_mb + ((size_t)b * SS + (q0 + rb + 16 + g)) * 32;  // mf1 r0
    const uint32_t* mb3 = g_mb + ((size_t)b * SS + (q0 + rb + 16 + g + 8)) * 32;

    const int l0 = (g << 2) | (tig >> 1);
    const int l1 = l0 + 2;
    const bool odd = tig & 1;

    for (int t = 0; t < NT; t++) {
        const int st = t & 1;
        if (t + 1 < NT) {
            const float* kb2 = kb + (size_t)(t + 1) * 64 * HD;
            const float* vb2 = vb + (size_t)(t + 1) * 64 * HD;
            float* Kd = Ks + (st ^ 1) * 4352;
            float* Vd = Vs + (st ^ 1) * 4608;
#pragma unroll
            for (int j = 0; j < 8; j++) {
                int idx = tid + j * 128;
                int rr = idx >> 4, c4 = idx & 15;
                cpa16(&Kd[rr * KLD + c4 * 4], kb2 + (size_t)rr * HD + c4 * 4);
                cpa16(&Vd[rr * VLD + c4 * 4], vb2 + (size_t)rr * HD + c4 * 4);
            }
        }
        CP_COMMIT();

        // mask words for this tile (2 words per row)
        uint2 mw[4];
        mw[0] = *(const uint2*)(mb0 + t * 2);
        mw[1] = *(const uint2*)(mb1 + t * 2);
        mw[2] = *(const uint2*)(mb2 + t * 2);
        mw[3] = *(const uint2*)(mb3 + t * 2);

        CP_WAIT(1);
        __syncthreads();

        const float* Kst = Ks + st * 4352;
        const float* Vst = Vs + st * 4608;

        // ---- S = Q @ K^T (both m-frags share each K b-frag) ----
        float s[2][8][4];
#pragma unroll
        for (int j = 0; j < 8; j++) {
            s[0][j][0] = s[0][j][1] = s[0][j][2] = s[0][j][3] = 0.0f;
            s[1][j][0] = s[1][j][1] = s[1][j][2] = s[1][j][3] = 0.0f;
            const float* krow = &Kst[(j * 8 + g) * KLD];
#pragma unroll
            for (int kk = 0; kk < 8; kk++) {
                const float b0 = krow[kk * 8 + tig];
                const float b1 = krow[kk * 8 + tig + 4];
                mma8(s[0][j], qf[0][kk], b0, b1);
                mma8(s[1][j], qf[1][kk], b0, b1);
            }
        }

        // ---- bitmask ----
#pragma unroll
        for (int mf = 0; mf < 2; mf++) {
#pragma unroll
            for (int j = 0; j < 8; j++) {
                const int bit = (j * 8 + 2 * tig) & 31;
                const uint32_t wa = (j < 4) ? mw[mf * 2].x     : mw[mf * 2].y;
                const uint32_t wb = (j < 4) ? mw[mf * 2 + 1].x : mw[mf * 2 + 1].y;
                if (!((wa >> bit) & 1))       s[mf][j][0] = -1e20f;
                if (!((wa >> (bit + 1)) & 1)) s[mf][j][1] = -1e20f;
                if (!((wb >> bit) & 1))       s[mf][j][2] = -1e20f;
                if (!((wb >> (bit + 1)) & 1)) s[mf][j][3] = -1e20f;
            }
        }

        // ---- online softmax per m-frag ----
#pragma unroll
        for (int mf = 0; mf < 2; mf++) {
            float mx0 = s[mf][0][0], mx1 = s[mf][0][2];
#pragma unroll
            for (int j = 0; j < 8; j++) {
                mx0 = fmaxf(mx0, fmaxf(s[mf][j][0], s[mf][j][1]));
                mx1 = fmaxf(mx1, fmaxf(s[mf][j][2], s[mf][j][3]));
            }
            mx0 = fmaxf(mx0, __shfl_xor_sync(0xffffffffu, mx0, 1));
            mx0 = fmaxf(mx0, __shfl_xor_sync(0xffffffffu, mx0, 2));
            mx1 = fmaxf(mx1, __shfl_xor_sync(0xffffffffu, mx1, 1));
            mx1 = fmaxf(mx1, __shfl_xor_sync(0xffffffffu, mx1, 2));
            const float mn0 = fmaxf(mi[mf][0], mx0);
            const float mn1 = fmaxf(mi[mf][1], mx1);
            const float a0 = __expf(mi[mf][0] - mn0);
            const float a1 = __expf(mi[mf][1] - mn1);
            float rs0 = 0.0f, rs1 = 0.0f;
#pragma unroll
            for (int j = 0; j < 8; j++) {
                s[mf][j][0] = __expf(s[mf][j][0] - mn0);
                s[mf][j][1] = __expf(s[mf][j][1] - mn0);
                s[mf][j][2] = __expf(s[mf][j][2] - mn1);
                s[mf][j][3] = __expf(s[mf][j][3] - mn1);
                rs0 += s[mf][j][0] + s[mf][j][1];
                rs1 += s[mf][j][2] + s[mf][j][3];
            }
            rs0 += __shfl_xor_sync(0xffffffffu, rs0, 1);
            rs0 += __shfl_xor_sync(0xffffffffu, rs0, 2);
            rs1 += __shfl_xor_sync(0xffffffffu, rs1, 1);
            rs1 += __shfl_xor_sync(0xffffffffu, rs1, 2);
            li[mf][0] = li[mf][0] * a0 + rs0;
            li[mf][1] = li[mf][1] * a1 + rs1;
            mi[mf][0] = mn0; mi[mf][1] = mn1;
#pragma unroll
            for (int j = 0; j < 8; j++) {
                o[mf][j][0] *= a0; o[mf][j][1] *= a0;
                o[mf][j][2] *= a1; o[mf][j][3] *= a1;
                s[mf][j][0] = wmma::__float_to_tf32(s[mf][j][0]);
                s[mf][j][1] = wmma::__float_to_tf32(s[mf][j][1]);
                s[mf][j][2] = wmma::__float_to_tf32(s[mf][j][2]);
                s[mf][j][3] = wmma::__float_to_tf32(s[mf][j][3]);
            }
        }

        // ---- O += P @ V (V b-frags shared across m-frags) ----
#pragma unroll
        for (int kk = 0; kk < 8; kk++) {
            float pa0[4], pa1[4];
            {
                float u0 = __shfl_sync(0xffffffffu, s[0][kk][0], l0);
                float u1 = __shfl_sync(0xffffffffu, s[0][kk][1], l0);
                float u2 = __shfl_sync(0xffffffffu, s[0][kk][2], l0);
                float u3 = __shfl_sync(0xffffffffu, s[0][kk][3], l0);
                float w0 = __shfl_sync(0xffffffffu, s[0][kk][0], l1);
                float w1 = __shfl_sync(0xffffffffu, s[0][kk][1], l1);
                float w2 = __shfl_sync(0xffffffffu, s[0][kk][2], l1);
                float w3 = __shfl_sync(0xffffffffu, s[0][kk][3], l1);
                pa0[0] = odd ? u1 : u0; pa0[1] = odd ? u3 : u2;
                pa0[2] = odd ? w1 : w0; pa0[3] = odd ? w3 : w2;
            }
            {
                float u0 = __shfl_sync(0xffffffffu, s[1][kk][0], l0);
                float u1 = __shfl_sync(0xffffffffu, s[1][kk][1], l0);
                float u2 = __shfl_sync(0xffffffffu, s[1][kk][2], l0);
                float u3 = __shfl_sync(0xffffffffu, s[1][kk][3], l0);
                float w0 = __shfl_sync(0xffffffffu, s[1][kk][0], l1);
                float w1 = __shfl_sync(0xffffffffu, s[1][kk][1], l1);
                float w2 = __shfl_sync(0xffffffffu, s[1][kk][2], l1);
                float w3 = __shfl_sync(0xffffffffu, s[1][kk][3], l1);
                pa1[0] = odd ? u1 : u0; pa1[1] = odd ? u3 : u2;
                pa1[2] = odd ? w1 : w0; pa1[3] = odd ? w3 : w2;
            }
            const float* v0 = &Vst[(kk * 8 + tig) * VLD];
            const float* v1 = &Vst[(kk * 8 + tig + 4) * VLD];
#pragma unroll
            for (int j = 0; j < 8; j++) {
                const float b0 = v0[j * 8 + g];
                const float b1 = v1[j * 8 + g];
                mma8(o[0][j], pa0, b0, b1);
                mma8(o[1][j], pa1, b0, b1);
            }
        }
        __syncthreads();
    }

    // ---- normalize + write (tf32-rounded for the next GEMM) ----
#pragma unroll
    for (int mf = 0; mf < 2; mf++) {
        const int r0 = rb + mf * 16 + g, r1 = r0 + 8;
        const float inv0 = 1.0f / li[mf][0], inv1 = 1.0f / li[mf][1];
        float* dst0 = g_ao + ((size_t)b * SS + (q0 + r0)) * DD + h * HD;
        float* dst1 = g_ao + ((size_t)b * SS + (q0 + r1)) * DD + h * HD;
#pragma unroll
        for (int j = 0; j < 8; j++) {
            float2 w0 = make_float2(wmma::__float_to_tf32(o[mf][j][0] * inv0),
                                    wmma::__float_to_tf32(o[mf][j][1] * inv0));
            float2 w1 = make_float2(wmma::__float_to_tf32(o[mf][j][2] * inv1),
                                    wmma::__float_to_tf32(o[mf][j][3] * inv1));
            *(float2*)&dst0[j * 8 + 2 * tig] = w0;
            *(float2*)&dst1[j * 8 + 2 * tig] = w1;
        }
    }
}

// ---------------------------------------------------------------------------
extern "C" void kernel_launch(void* const* d_in, const int* in_sizes, int n_in,
                              void* d_out, int out_size)
{
    const float* x    = (const float*)d_in[0];
    const int*   mask = (const int*)  d_in[1];
    const float* Wqkv = (const float*)d_in[2];
    const float* bqkv = (const float*)d_in[3];
    const float* Wo   = (const float*)d_in[4];
    const float* bo   = (const float*)d_in[5];
    float* out = (float*)d_out;
    (void)in_sizes; (void)n_in; (void)out_size;

    cudaFuncSetAttribute(attn_k, cudaFuncAttributeMaxDynamicSharedMemorySize,
                         ATTN_SMEM);
    cudaFuncSetAttribute(mgemm_k<0>, cudaFuncAttributeMaxDynamicSharedMemorySize,
                         GSMEM);
    cudaFuncSetAttribute(mgemm_k<1>, cudaFuncAttributeMaxDynamicSharedMemorySize,
                         GSMEM);

    // 0) pre-passes: tf32 rounding + mask bit-packing
    round_k<<<(BB * SS * DD / 4 + 255) / 256, 256>>>((const float4*)x, 0,
                                                     BB * SS * DD / 4);
    round_k<<<(3 * DD * DD / 4 + 255) / 256, 256>>>((const float4*)Wqkv, 1,
                                                    3 * DD * DD / 4);
    round_k<<<(DD * DD / 4 + 255) / 256, 256>>>((const float4*)Wo, 2,
                                                DD * DD / 4);
    maskpack_k<<<(BB * SS * (SS / 32) + 255) / 256, 256>>>(mask);

    // 1) QKV projection -> q/k/v (tf32-rounded, q pre-scaled)
    {
        dim3 grid(3 * DD / 128, (BB * SS) / 128);
        mgemm_k<0><<<grid, 128, GSMEM>>>(bqkv, nullptr, 3 * DD, DD);
    }

    // 2) Flash attention -> g_ao
    attn_k<<<dim3(SS / 128, HH, BB), 128, ATTN_SMEM>>>();

    // 3) Output projection -> d_out (fp32)
    {
        dim3 grid(DD / 128, (BB * SS) / 128);
        mgemm_k<1><<<grid, 128, GSMEM>>>(bo, out, DD, DD);
    }
}